// round 10
// baseline (speedup 1.0000x reference)
#include <cuda_runtime.h>
#include <cuda_bf16.h>
#include <cstdint>
#include <math.h>

// ===========================================================================
// S=2048, H=2048, COMP=1024, T=3072, KV_DIM=512, FF=5632, NH=32, NKV=8,
// HD=64, DEPTH=2. mma.sync.m16n8k16 bf16 hi/lo 3-product split everywhere.
// R9: bgemm re-tiled to 4 warps x (64x64) per 128x128 CTA (128 threads) to
//     cut LDSM fragment traffic 1.5x (smem-BW was co-limiting the mainloop).
// ===========================================================================

// -------------------- device-global scratch (no allocs) --------------------
__device__ float g_compressed[1024 * 2048];
__device__ float g_ct[1024 * 2048];
__device__ float g_gate[1024 * 5632];
__device__ float g_up[1024 * 5632];
__device__ float g_p0[1024 * 2048], g_p1[1024 * 2048];
__device__ float g_pk0[3072 * 512], g_pk1[3072 * 512];
__device__ float g_pv0[3072 * 512], g_pv1[3072 * 512];

__device__ __nv_bfloat16 g_res_hi[3072 * 2048], g_res_lo[3072 * 2048];
__device__ __nv_bfloat16 g_ct_hi[1024 * 2048], g_ct_lo[1024 * 2048];
__device__ __nv_bfloat16 g_ao_hi[1024 * 2048], g_ao_lo[1024 * 2048];
__device__ __nv_bfloat16 g_ga_hi[1024 * 5632], g_ga_lo[1024 * 5632];
__device__ __nv_bfloat16 g_hT_hi[2048 * 2048], g_hT_lo[2048 * 2048];

__device__ __nv_bfloat16 g_q_hi[1024 * 2048], g_q_lo[1024 * 2048];
__device__ __nv_bfloat16 g_k_hi[3072 * 512],  g_k_lo[3072 * 512];
__device__ __nv_bfloat16 g_v_hi[3072 * 512],  g_v_lo[3072 * 512];

__device__ __nv_bfloat16 g_cw_hi[1024 * 2048], g_cw_lo[1024 * 2048];
__device__ __nv_bfloat16 g_qw_hi[2048 * 2048], g_qw_lo[2048 * 2048];
__device__ __nv_bfloat16 g_kw_hi[512 * 2048],  g_kw_lo[512 * 2048];
__device__ __nv_bfloat16 g_vw_hi[512 * 2048],  g_vw_lo[512 * 2048];
__device__ __nv_bfloat16 g_ow_hi[2048 * 2048], g_ow_lo[2048 * 2048];
__device__ __nv_bfloat16 g_gw_hi[5632 * 2048], g_gw_lo[5632 * 2048];
__device__ __nv_bfloat16 g_uw_hi[5632 * 2048], g_uw_lo[5632 * 2048];
__device__ __nv_bfloat16 g_dw_hi[2048 * 5632], g_dw_lo[2048 * 5632];

// -------------------- helpers --------------------
__device__ __forceinline__ uint32_t smem_u32(const void* p) {
    return (uint32_t)__cvta_generic_to_shared(p);
}

#define LDSM_X4(r0, r1, r2, r3, addr)                                          \
    asm volatile("ldmatrix.sync.aligned.m8n8.x4.shared.b16 {%0,%1,%2,%3}, [%4];" \
                 : "=r"(r0), "=r"(r1), "=r"(r2), "=r"(r3) : "r"(addr))
#define LDSM_X4_T(r0, r1, r2, r3, addr)                                        \
    asm volatile("ldmatrix.sync.aligned.m8n8.x4.trans.shared.b16 {%0,%1,%2,%3}, [%4];" \
                 : "=r"(r0), "=r"(r1), "=r"(r2), "=r"(r3) : "r"(addr))

#define MMA_BF16(ac, ar, br)                                                   \
    asm volatile(                                                              \
        "mma.sync.aligned.m16n8k16.row.col.f32.bf16.bf16.f32 "                 \
        "{%0,%1,%2,%3},{%4,%5,%6,%7},{%8,%9},{%0,%1,%2,%3};"                   \
        : "+f"((ac)[0]), "+f"((ac)[1]), "+f"((ac)[2]), "+f"((ac)[3])           \
        : "r"((ar)[0]), "r"((ar)[1]), "r"((ar)[2]), "r"((ar)[3]),              \
          "r"((br)[0]), "r"((br)[1]))

#define CP_ASYNC16(dst, src)                                                   \
    asm volatile("cp.async.cg.shared.global [%0], [%1], 16;" :: "r"(dst), "l"(src))
#define CP_COMMIT() asm volatile("cp.async.commit_group;")
#define CP_WAIT1()  asm volatile("cp.async.wait_group 1;")

__device__ __forceinline__ uint32_t pack_bf2(float x, float y) {
    __nv_bfloat162 h = __floats2bfloat162_rn(x, y);
    return *(uint32_t*)&h;
}

// ==================== HMMA split-bf16 GEMM body (4 warps, 64x64/warp) ======
// C = (Ahi+Alo)[M,Klen] @ (Bhi+Blo)[N,Klen]^T (row stride K).
// BM=BN=128, BK=32, 128 threads, 3-stage cp.async, conflict-free swizzle.
__device__ __forceinline__ void load_stage(
    uint32_t sb, int kc, int tid, int m0, int n0, int K,
    const __nv_bfloat16* __restrict__ Ahi, const __nv_bfloat16* __restrict__ Alo,
    const __nv_bfloat16* __restrict__ Bhi, const __nv_bfloat16* __restrict__ Blo)
{
    const int kb = kc * 32;
#pragma unroll
    for (int i = 0; i < 4; i++) {
        int f = tid + i * 128;           // 512 x 16B chunks per buffer
        int r = f >> 2, c = f & 3;
        uint32_t off = (uint32_t)(r * 64) +
                       (uint32_t)((c * 16) ^ (((r >> 1) & 3) << 4));
        size_t ga = (size_t)(m0 + r) * K + kb + c * 8;
        size_t gb = (size_t)(n0 + r) * K + kb + c * 8;
        CP_ASYNC16(sb + off,         Ahi + ga);
        CP_ASYNC16(sb + 8192 + off,  Alo + ga);
        CP_ASYNC16(sb + 16384 + off, Bhi + gb);
        CP_ASYNC16(sb + 24576 + off, Blo + gb);
    }
}

template <int OUT>
__device__ __forceinline__ void bgemm_body(
    const __nv_bfloat16* __restrict__ Ahi, const __nv_bfloat16* __restrict__ Alo,
    const __nv_bfloat16* __restrict__ Bhi, const __nv_bfloat16* __restrict__ Blo,
    float* __restrict__ C,
    __nv_bfloat16* __restrict__ Chi, __nv_bfloat16* __restrict__ Clo,
    int N, int K, int Klen, int m0, int n0)
{
    extern __shared__ char dsm[];
    const int tid = threadIdx.x;
    const int wid = tid >> 5, lid = tid & 31;
    const int wm = wid & 1, wn = wid >> 1;       // 2x2 warp grid, 64x64 each
    const uint32_t sbase = smem_u32(dsm);

    const int arow = wm * 64 + (lid & 7) + ((lid >> 3) & 1) * 8;   // +mt*16
    const uint32_t a_base = (uint32_t)(arow * 64);
    const uint32_t a_sw = (uint32_t)(((arow >> 1) & 3) << 4);
    const uint32_t a_k = (uint32_t)((lid >> 4) & 1) * 16;

    const int brow = wn * 64 + (lid & 7) + ((lid >> 4) & 1) * 8;   // +p*16
    const uint32_t b_base = (uint32_t)(brow * 64);
    const uint32_t b_sw = (uint32_t)(((brow >> 1) & 3) << 4);
    const uint32_t b_k = (uint32_t)((lid >> 3) & 1) * 16;

    float acc[4][8][4];
#pragma unroll
    for (int mt = 0; mt < 4; mt++)
#pragma unroll
        for (int nt = 0; nt < 8; nt++)
#pragma unroll
            for (int e = 0; e < 4; e++) acc[mt][nt][e] = 0.f;

    const int NK = Klen / 32;
    load_stage(sbase, 0, tid, m0, n0, K, Ahi, Alo, Bhi, Blo);
    CP_COMMIT();
    load_stage(sbase + 32768, 1, tid, m0, n0, K, Ahi, Alo, Bhi, Blo);
    CP_COMMIT();

    for (int kc = 0; kc < NK; kc++) {
        CP_WAIT1();
        __syncthreads();
        if (kc + 2 < NK)
            load_stage(sbase + (uint32_t)((kc + 2) % 3) * 32768, kc + 2, tid,
                       m0, n0, K, Ahi, Alo, Bhi, Blo);
        CP_COMMIT();

        const uint32_t st = sbase + (uint32_t)(kc % 3) * 32768;
#pragma unroll
        for (int ks = 0; ks < 2; ks++) {
            const uint32_t ako = (a_k + (uint32_t)ks * 32) ^ a_sw;
            const uint32_t bko = (b_k + (uint32_t)ks * 32) ^ b_sw;
            uint32_t ah[4][4], al[4][4], bb[8][2];
#pragma unroll
            for (int mt = 0; mt < 4; mt++) {
                LDSM_X4(ah[mt][0], ah[mt][1], ah[mt][2], ah[mt][3],
                        st + a_base + (uint32_t)mt * 1024 + ako);
                LDSM_X4(al[mt][0], al[mt][1], al[mt][2], al[mt][3],
                        st + 8192 + a_base + (uint32_t)mt * 1024 + ako);
            }
            // B-hi
#pragma unroll
            for (int p = 0; p < 4; p++) {
                LDSM_X4(bb[2*p][0], bb[2*p][1], bb[2*p+1][0], bb[2*p+1][1],
                        st + 16384 + b_base + (uint32_t)p * 1024 + bko);
            }
#pragma unroll
            for (int nt = 0; nt < 8; nt++)
#pragma unroll
                for (int mt = 0; mt < 4; mt++)
                    MMA_BF16(acc[mt][nt], ah[mt], bb[nt]);
#pragma unroll
            for (int nt = 0; nt < 8; nt++)
#pragma unroll
                for (int mt = 0; mt < 4; mt++)
                    MMA_BF16(acc[mt][nt], al[mt], bb[nt]);
            // B-lo (reuse bb regs)
#pragma unroll
            for (int p = 0; p < 4; p++) {
                LDSM_X4(bb[2*p][0], bb[2*p][1], bb[2*p+1][0], bb[2*p+1][1],
                        st + 24576 + b_base + (uint32_t)p * 1024 + bko);
            }
#pragma unroll
            for (int nt = 0; nt < 8; nt++)
#pragma unroll
                for (int mt = 0; mt < 4; mt++)
                    MMA_BF16(acc[mt][nt], ah[mt], bb[nt]);
        }
    }

    const int grow0 = m0 + wm * 64 + (lid >> 2);
    const int gcol0 = n0 + wn * 64 + (lid & 3) * 2;
#pragma unroll
    for (int mt = 0; mt < 4; mt++) {
#pragma unroll
        for (int nt = 0; nt < 8; nt++) {
            int r0 = grow0 + mt * 16;
            int c0 = gcol0 + nt * 8;
            float2 v0 = make_float2(acc[mt][nt][0], acc[mt][nt][1]);
            float2 v1 = make_float2(acc[mt][nt][2], acc[mt][nt][3]);
            if (OUT == 0) {
                *(float2*)(C + (size_t)r0 * N + c0) = v0;
                *(float2*)(C + (size_t)(r0 + 8) * N + c0) = v1;
            } else {
                uint32_t h0 = pack_bf2(v0.x, v0.y);
                uint32_t h1 = pack_bf2(v1.x, v1.y);
                *(uint32_t*)(Chi + (size_t)r0 * N + c0) = h0;
                *(uint32_t*)(Chi + (size_t)(r0 + 8) * N + c0) = h1;
                __nv_bfloat162 hh0 = *(__nv_bfloat162*)&h0;
                __nv_bfloat162 hh1 = *(__nv_bfloat162*)&h1;
                *(uint32_t*)(Clo + (size_t)r0 * N + c0) =
                    pack_bf2(v0.x - __bfloat162float(hh0.x),
                             v0.y - __bfloat162float(hh0.y));
                *(uint32_t*)(Clo + (size_t)(r0 + 8) * N + c0) =
                    pack_bf2(v1.x - __bfloat162float(hh1.x),
                             v1.y - __bfloat162float(hh1.y));
            }
        }
    }
}

// split-K x2 GEMM: grid = 2 * (M/128)*(N/128); halves write P0 / P1.
__global__ __launch_bounds__(128, 2) void bgemm_splitk(
    const __nv_bfloat16* __restrict__ Ahi, const __nv_bfloat16* __restrict__ Alo,
    const __nv_bfloat16* __restrict__ Bhi, const __nv_bfloat16* __restrict__ Blo,
    float* __restrict__ P0, float* __restrict__ P1,
    int N, int K, int Khalf)
{
    const int per = gridDim.x >> 1;
    int id = blockIdx.x;
    const int half = (id >= per) ? 1 : 0;
    if (half) id -= per;
    const int ntn = N >> 7;
    const int m0 = (id / ntn) * 128, n0 = (id % ntn) * 128;
    const int ko = half * Khalf;
    bgemm_body<0>(Ahi + ko, Alo + ko, Bhi + ko, Blo + ko,
                  half ? P1 : P0, nullptr, nullptr, N, K, Khalf, m0, n0);
}

// q (full-K) + k/v (split-K x2), one launch.
__global__ __launch_bounds__(128, 2) void bgemm_qkv(
    const __nv_bfloat16* __restrict__ ct_hi, const __nv_bfloat16* __restrict__ ct_lo,
    const __nv_bfloat16* __restrict__ res_hi, const __nv_bfloat16* __restrict__ res_lo,
    const __nv_bfloat16* __restrict__ qw_hi, const __nv_bfloat16* __restrict__ qw_lo,
    const __nv_bfloat16* __restrict__ kw_hi, const __nv_bfloat16* __restrict__ kw_lo,
    const __nv_bfloat16* __restrict__ vw_hi, const __nv_bfloat16* __restrict__ vw_lo,
    __nv_bfloat16* __restrict__ q_hi, __nv_bfloat16* __restrict__ q_lo,
    float* __restrict__ pk0, float* __restrict__ pk1,
    float* __restrict__ pv0, float* __restrict__ pv1)
{
    int id = blockIdx.x;
    if (id < 128) {
        bgemm_body<1>(ct_hi, ct_lo, qw_hi, qw_lo, nullptr, q_hi, q_lo,
                      2048, 2048, 2048, (id >> 4) * 128, (id & 15) * 128);
    } else {
        int id2 = id - 128;
        const int part = id2 / 96;       // 0:k-h0 1:k-h1 2:v-h0 3:v-h1
        const int t = id2 % 96;
        const int half = part & 1, isv = part >> 1;
        const int ko = half * 1024;
        const __nv_bfloat16* bh = (isv ? vw_hi : kw_hi) + ko;
        const __nv_bfloat16* bl = (isv ? vw_lo : kw_lo) + ko;
        float* P = isv ? (half ? pv1 : pv0) : (half ? pk1 : pk0);
        bgemm_body<0>(res_hi + ko, res_lo + ko, bh, bl, P, nullptr, nullptr,
                      512, 2048, 1024, (t >> 2) * 128, (t & 3) * 128);
    }
}

// gate + up in one launch (704 tiles, fp32 out).
__global__ __launch_bounds__(128, 2) void bgemm_gateup(
    const __nv_bfloat16* __restrict__ ct_hi, const __nv_bfloat16* __restrict__ ct_lo,
    const __nv_bfloat16* __restrict__ gw_hi, const __nv_bfloat16* __restrict__ gw_lo,
    const __nv_bfloat16* __restrict__ uw_hi, const __nv_bfloat16* __restrict__ uw_lo,
    float* __restrict__ gate, float* __restrict__ up)
{
    int id = blockIdx.x;
    if (id < 352) {
        bgemm_body<0>(ct_hi, ct_lo, gw_hi, gw_lo, gate, nullptr, nullptr,
                      5632, 2048, 2048, (id / 44) * 128, (id % 44) * 128);
    } else {
        id -= 352;
        bgemm_body<0>(ct_hi, ct_lo, uw_hi, uw_lo, up, nullptr, nullptr,
                      5632, 2048, 2048, (id / 44) * 128, (id % 44) * 128);
    }
}

// ==================== split-K reduce ====================
template <int BIAS, int CT, int OF32, int OSPLIT>
__global__ void reduce2(const float* __restrict__ P0, const float* __restrict__ P1,
                        const float* __restrict__ aux, float* __restrict__ C,
                        __nv_bfloat16* __restrict__ hi, __nv_bfloat16* __restrict__ lo,
                        int n4, int rowdiv)
{
    int i = blockIdx.x * 1024 + threadIdx.x;
#pragma unroll
    for (int u = 0; u < 4; u++, i += 256) {
        if (i < n4) {
            float4 a = ((const float4*)P0)[i];
            float4 b = ((const float4*)P1)[i];
            float4 v = make_float4(a.x + b.x, a.y + b.y, a.z + b.z, a.w + b.w);
            if (BIAS) {
                float bb = aux[i / rowdiv];
                v.x += bb; v.y += bb; v.z += bb; v.w += bb;
            }
            if (CT) {
                float4 c = ((const float4*)aux)[i];
                v.x += c.x; v.y += c.y; v.z += c.z; v.w += c.w;
            }
            if (OF32) ((float4*)C)[i] = v;
            if (OSPLIT) {
                uint32_t h0 = pack_bf2(v.x, v.y), h1 = pack_bf2(v.z, v.w);
                ((uint32_t*)hi)[i * 2]     = h0;
                ((uint32_t*)hi)[i * 2 + 1] = h1;
                __nv_bfloat162 a0 = *(__nv_bfloat162*)&h0;
                __nv_bfloat162 a1 = *(__nv_bfloat162*)&h1;
                ((uint32_t*)lo)[i * 2] =
                    pack_bf2(v.x - __bfloat162float(a0.x), v.y - __bfloat162float(a0.y));
                ((uint32_t*)lo)[i * 2 + 1] =
                    pack_bf2(v.z - __bfloat162float(a1.x), v.w - __bfloat162float(a1.y));
            }
        }
    }
}

// ==================== HMMA split-bf16 flash attention (2-stage, 4/SM) ======
__global__ __launch_bounds__(128, 4) void attn_mma(
    const __nv_bfloat16* __restrict__ Qhi, const __nv_bfloat16* __restrict__ Qlo,
    const __nv_bfloat16* __restrict__ Khi, const __nv_bfloat16* __restrict__ Klo,
    const __nv_bfloat16* __restrict__ Vhi, const __nv_bfloat16* __restrict__ Vlo,
    __nv_bfloat16* __restrict__ Ohi, __nv_bfloat16* __restrict__ Olo)
{
    extern __shared__ char sm[];
    const int tid = threadIdx.x;
    const int wid = tid >> 5, lid = tid & 31;
    const int q0 = blockIdx.x * 64;
    const int head = blockIdx.y;
    const int kvoff = (head >> 2) * 64;
    const uint32_t sb = smem_u32(sm);
    const uint32_t sQh = sb, sQl = sb + 8192;
    const uint32_t sKV = sb + 16384;

#pragma unroll
    for (int i = 0; i < 4; i++) {
        int f = tid + i * 128;
        int r = f >> 3, c = f & 7;
        uint32_t off = (uint32_t)(r * 128) + (uint32_t)((c * 16) ^ ((r & 7) << 4));
        size_t g = (size_t)(q0 + r) * 2048 + head * 64 + c * 8;
        CP_ASYNC16(sQh + off, Qhi + g);
        CP_ASYNC16(sQl + off, Qlo + g);
    }
    CP_COMMIT();

#define ISSUE_KV(t0, st)                                                       \
    {                                                                          \
        uint32_t s_ = sKV + (uint32_t)(st) * 16384;                            \
        _Pragma("unroll")                                                      \
        for (int i_ = 0; i_ < 2; i_++) {                                       \
            int f_ = tid + i_ * 128;                                           \
            int r_ = f_ >> 3, c_ = f_ & 7;                                     \
            uint32_t o_ = (uint32_t)(r_ * 128) +                               \
                          (uint32_t)((c_ * 16) ^ ((r_ & 7) << 4));             \
            size_t g_ = (size_t)((t0) + r_) * 512 + kvoff + c_ * 8;            \
            CP_ASYNC16(s_ + o_,         Khi + g_);                             \
            CP_ASYNC16(s_ + 4096 + o_,  Klo + g_);                             \
            CP_ASYNC16(s_ + 8192 + o_,  Vhi + g_);                             \
            CP_ASYNC16(s_ + 12288 + o_, Vlo + g_);                             \
        }                                                                      \
    }

    ISSUE_KV(0, 0);  CP_COMMIT();
    ISSUE_KV(32, 1); CP_COMMIT();

    CP_WAIT1();
    __syncthreads();

    uint32_t qh[4][4], ql[4][4];
    {
        const int ar = (lid & 7) + ((lid >> 3) & 1) * 8;
        const int row = wid * 16 + ar;
        const uint32_t khalf = (uint32_t)((lid >> 4) & 1) * 16;
#pragma unroll
        for (int ks = 0; ks < 4; ks++) {
            uint32_t off = (uint32_t)(row * 128) +
                           ((khalf + (uint32_t)ks * 32) ^ ((uint32_t)(ar & 7) << 4));
            LDSM_X4(qh[ks][0], qh[ks][1], qh[ks][2], qh[ks][3], sQh + off);
            LDSM_X4(ql[ks][0], ql[ks][1], ql[ks][2], ql[ks][3], sQl + off);
        }
    }

    float acc_o[8][4];
#pragma unroll
    for (int d = 0; d < 8; d++)
#pragma unroll
        for (int e = 0; e < 4; e++) acc_o[d][e] = 0.f;
    float mr0 = -1e30f, mr1 = -1e30f, lr0 = 0.f, lr1 = 0.f;

    const int brS = (lid & 7) + ((lid >> 4) & 1) * 8;
    const uint32_t bkS = (uint32_t)((lid >> 3) & 1) * 16;
    const int trV = (lid & 7) + ((lid >> 3) & 1) * 8;
    const uint32_t dkV = (uint32_t)((lid >> 4) & 1) * 16;

    for (int t = 0; t < 96; t++) {
        const uint32_t st = sKV + (uint32_t)(t & 1) * 16384;

        float s[4][4];
#pragma unroll
        for (int nt = 0; nt < 4; nt++)
#pragma unroll
            for (int e = 0; e < 4; e++) s[nt][e] = 0.f;
#pragma unroll
        for (int ks = 0; ks < 4; ks++) {
            uint32_t bh[4][2], bl[4][2];
#pragma unroll
            for (int p = 0; p < 2; p++) {
                int rr = p * 16 + brS;
                uint32_t off = (uint32_t)(rr * 128) +
                               ((bkS + (uint32_t)ks * 32) ^ ((uint32_t)(rr & 7) << 4));
                LDSM_X4(bh[2*p][0], bh[2*p][1], bh[2*p+1][0], bh[2*p+1][1], st + off);
                LDSM_X4(bl[2*p][0], bl[2*p][1], bl[2*p+1][0], bl[2*p+1][1], st + 4096 + off);
            }
#pragma unroll
            for (int nt = 0; nt < 4; nt++) {
                MMA_BF16(s[nt], qh[ks], bh[nt]);
                MMA_BF16(s[nt], qh[ks], bl[nt]);
                MMA_BF16(s[nt], ql[ks], bh[nt]);
            }
        }

        float mn0 = mr0, mn1 = mr1;
#pragma unroll
        for (int nt = 0; nt < 4; nt++) {
            s[nt][0] *= 0.125f; s[nt][1] *= 0.125f;
            s[nt][2] *= 0.125f; s[nt][3] *= 0.125f;
            mn0 = fmaxf(mn0, fmaxf(s[nt][0], s[nt][1]));
            mn1 = fmaxf(mn1, fmaxf(s[nt][2], s[nt][3]));
        }
        mn0 = fmaxf(mn0, __shfl_xor_sync(0xffffffffu, mn0, 1));
        mn0 = fmaxf(mn0, __shfl_xor_sync(0xffffffffu, mn0, 2));
        mn1 = fmaxf(mn1, __shfl_xor_sync(0xffffffffu, mn1, 1));
        mn1 = fmaxf(mn1, __shfl_xor_sync(0xffffffffu, mn1, 2));
        float f0 = __expf(mr0 - mn0), f1 = __expf(mr1 - mn1);
        mr0 = mn0; mr1 = mn1;
        float ps0 = 0.f, ps1 = 0.f;
#pragma unroll
        for (int nt = 0; nt < 4; nt++) {
            s[nt][0] = __expf(s[nt][0] - mn0);
            s[nt][1] = __expf(s[nt][1] - mn0);
            s[nt][2] = __expf(s[nt][2] - mn1);
            s[nt][3] = __expf(s[nt][3] - mn1);
            ps0 += s[nt][0] + s[nt][1];
            ps1 += s[nt][2] + s[nt][3];
        }
        lr0 = lr0 * f0 + ps0;
        lr1 = lr1 * f1 + ps1;
#pragma unroll
        for (int d = 0; d < 8; d++) {
            acc_o[d][0] *= f0; acc_o[d][1] *= f0;
            acc_o[d][2] *= f1; acc_o[d][3] *= f1;
        }

#pragma unroll
        for (int j = 0; j < 2; j++) {
            uint32_t ah[4], al[4];
            {
                float p00 = s[2*j][0],   p01 = s[2*j][1];
                float p02 = s[2*j][2],   p03 = s[2*j][3];
                float p10 = s[2*j+1][0], p11 = s[2*j+1][1];
                float p12 = s[2*j+1][2], p13 = s[2*j+1][3];
                ah[0] = pack_bf2(p00, p01); ah[1] = pack_bf2(p02, p03);
                ah[2] = pack_bf2(p10, p11); ah[3] = pack_bf2(p12, p13);
#pragma unroll
                for (int e = 0; e < 4; e++) {
                    __nv_bfloat162 hh = *(__nv_bfloat162*)&ah[e];
                    float x0, x1;
                    if (e == 0) { x0 = p00; x1 = p01; }
                    else if (e == 1) { x0 = p02; x1 = p03; }
                    else if (e == 2) { x0 = p10; x1 = p11; }
                    else { x0 = p12; x1 = p13; }
                    al[e] = pack_bf2(x0 - __bfloat162float(hh.x),
                                     x1 - __bfloat162float(hh.y));
                }
            }
            const int rr = j * 16 + trV;
#pragma unroll
            for (int dp = 0; dp < 4; dp++) {
                uint32_t off = (uint32_t)(rr * 128) +
                               ((dkV + (uint32_t)dp * 32) ^ ((uint32_t)(rr & 7) << 4));
                uint32_t vh[4], vl[4];
                LDSM_X4_T(vh[0], vh[1], vh[2], vh[3], st + 8192 + off);
                LDSM_X4_T(vl[0], vl[1], vl[2], vl[3], st + 12288 + off);
                uint32_t b0h[2] = {vh[0], vh[1]}, b1h[2] = {vh[2], vh[3]};
                uint32_t b0l[2] = {vl[0], vl[1]}, b1l[2] = {vl[2], vl[3]};
                MMA_BF16(acc_o[2*dp],   ah, b0h);
                MMA_BF16(acc_o[2*dp],   ah, b0l);
                MMA_BF16(acc_o[2*dp],   al, b0h);
                MMA_BF16(acc_o[2*dp+1], ah, b1h);
                MMA_BF16(acc_o[2*dp+1], ah, b1l);
                MMA_BF16(acc_o[2*dp+1], al, b1h);
            }
        }

        __syncthreads();
        if (t + 2 < 96) ISSUE_KV((t + 2) * 32, t & 1);
        CP_COMMIT();
        if (t + 1 < 96) { CP_WAIT1(); __syncthreads(); }
    }

    lr0 += __shfl_xor_sync(0xffffffffu, lr0, 1);
    lr0 += __shfl_xor_sync(0xffffffffu, lr0, 2);
    lr1 += __shfl_xor_sync(0xffffffffu, lr1, 1);
    lr1 += __shfl_xor_sync(0xffffffffu, lr1, 2);
    float il0 = 1.f / lr0, il1 = 1.f / lr1;
    const int row0 = q0 + wid * 16 + (lid >> 2);
    const int col0 = head * 64 + (lid & 3) * 2;
#pragma unroll
    for (int d = 0; d < 8; d++) {
        int col = col0 + d * 8;
        float o0 = acc_o[d][0] * il0, o1 = acc_o[d][1] * il0;
        float o2 = acc_o[d][2] * il1, o3 = acc_o[d][3] * il1;
        uint32_t h0 = pack_bf2(o0, o1), h1 = pack_bf2(o2, o3);
        *(uint32_t*)(Ohi + (size_t)row0 * 2048 + col) = h0;
        *(uint32_t*)(Ohi + (size_t)(row0 + 8) * 2048 + col) = h1;
        __nv_bfloat162 hh0 = *(__nv_bfloat162*)&h0;
        __nv_bfloat162 hh1 = *(__nv_bfloat162*)&h1;
        *(uint32_t*)(Olo + (size_t)row0 * 2048 + col) =
            pack_bf2(o0 - __bfloat162float(hh0.x), o1 - __bfloat162float(hh0.y));
        *(uint32_t*)(Olo + (size_t)(row0 + 8) * 2048 + col) =
            pack_bf2(o2 - __bfloat162float(hh1.x), o3 - __bfloat162float(hh1.y));
    }
}

// -------------------- conversion / elementwise kernels --------------------
__global__ void split_kernel(const float* __restrict__ x,
                             __nv_bfloat16* __restrict__ hi,
                             __nv_bfloat16* __restrict__ lo, int n4)
{
    int i = blockIdx.x * 1024 + threadIdx.x;
#pragma unroll
    for (int u = 0; u < 4; u++, i += 256) {
        if (i < n4) {
            float4 v = ((const float4*)x)[i];
            uint32_t h0 = pack_bf2(v.x, v.y), h1 = pack_bf2(v.z, v.w);
            ((uint32_t*)hi)[i * 2]     = h0;
            ((uint32_t*)hi)[i * 2 + 1] = h1;
            __nv_bfloat162 a0 = *(__nv_bfloat162*)&h0;
            __nv_bfloat162 a1 = *(__nv_bfloat162*)&h1;
            ((uint32_t*)lo)[i * 2] =
                pack_bf2(v.x - __bfloat162float(a0.x), v.y - __bfloat162float(a0.y));
            ((uint32_t*)lo)[i * 2 + 1] =
                pack_bf2(v.z - __bfloat162float(a1.x), v.w - __bfloat162float(a1.y));
        }
    }
}

__global__ void transpose_split(const float* __restrict__ x,
                                __nv_bfloat16* __restrict__ hiT,
                                __nv_bfloat16* __restrict__ loT, int R, int C)
{
    __shared__ float t[32][33];
    int c0 = blockIdx.x * 32, r0 = blockIdx.y * 32;
    for (int i = threadIdx.y; i < 32; i += 8)
        t[i][threadIdx.x] = x[(size_t)(r0 + i) * C + c0 + threadIdx.x];
    __syncthreads();
    for (int i = threadIdx.y; i < 32; i += 8) {
        float v = t[threadIdx.x][i];
        __nv_bfloat16 h = __float2bfloat16(v);
        size_t o = (size_t)(c0 + i) * R + r0 + threadIdx.x;
        hiT[o] = h;
        loT[o] = __float2bfloat16(v - __bfloat162float(h));
    }
}

__global__ void rmsnorm_kernel(const float* __restrict__ x,
                               const float* __restrict__ w,
                               float* __restrict__ y,
                               __nv_bfloat16* __restrict__ yhi,
                               __nv_bfloat16* __restrict__ ylo)
{
    const int row = blockIdx.x;
    const float* xr = x + (size_t)row * 2048;
    float ss = 0.f;
    for (int i = threadIdx.x; i < 2048; i += 256) { float v = xr[i]; ss += v * v; }
    __shared__ float red[256];
    red[threadIdx.x] = ss;
    __syncthreads();
    for (int s = 128; s > 0; s >>= 1) {
        if (threadIdx.x < s) red[threadIdx.x] += red[threadIdx.x + s];
        __syncthreads();
    }
    __shared__ float inv;
    if (threadIdx.x == 0) inv = rsqrtf(red[0] * (1.f / 2048.f) + 1e-6f);
    __syncthreads();
    float iv = inv;
    for (int i = threadIdx.x; i < 2048; i += 256) {
        float v = xr[i] * iv * w[i];
        size_t o = (size_t)row * 2048 + i;
        y[o] = v;
        __nv_bfloat16 h = __float2bfloat16(v);
        yhi[o] = h;
        ylo[o] = __float2bfloat16(v - __bfloat162float(h));
    }
}

__global__ void swiglu_split(const float* __restrict__ g, const float* __restrict__ u,
                             __nv_bfloat16* __restrict__ hi, __nv_bfloat16* __restrict__ lo,
                             int n)
{
    int i = blockIdx.x * blockDim.x + threadIdx.x;
    if (i < n) {
        float x = g[i];
        float v = (x / (1.f + __expf(-x))) * u[i];
        __nv_bfloat16 h = __float2bfloat16(v);
        hi[i] = h;
        lo[i] = __float2bfloat16(v - __bfloat162float(h));
    }
}

// -------------------- orchestration --------------------
static const int SMEM_GEMM = 3 * 32768;          // 96KB
static const int SMEM_ATTN = 16384 + 2 * 16384;  // 48KB -> 4 CTAs/SM

extern "C" void kernel_launch(void* const* d_in, const int* in_sizes, int n_in,
                              void* d_out, int out_size)
{
    (void)in_sizes; (void)n_in; (void)out_size;
    const float* hidden      = (const float*)d_in[0];
    const float* comp_w      = (const float*)d_in[1];
    const float* comp_b      = (const float*)d_in[2];
    const float* q_w         = (const float*)d_in[3];
    const float* k_w         = (const float*)d_in[4];
    const float* v_w         = (const float*)d_in[5];
    const float* o_w         = (const float*)d_in[6];
    const float* attn_norm_w = (const float*)d_in[7];
    const float* mlp_norm_w  = (const float*)d_in[8];
    const float* gate_w      = (const float*)d_in[9];
    const float* up_w        = (const float*)d_in[10];
    const float* down_w      = (const float*)d_in[11];
    float* out = (float*)d_out;

    cudaFuncSetAttribute(bgemm_splitk, cudaFuncAttributeMaxDynamicSharedMemorySize, SMEM_GEMM);
    cudaFuncSetAttribute(bgemm_qkv,    cudaFuncAttributeMaxDynamicSharedMemorySize, SMEM_GEMM);
    cudaFuncSetAttribute(bgemm_gateup, cudaFuncAttributeMaxDynamicSharedMemorySize, SMEM_GEMM);
    cudaFuncSetAttribute(attn_mma,     cudaFuncAttributeMaxDynamicSharedMemorySize, SMEM_ATTN);

    float *compressed, *ct, *gate, *up, *p0, *p1, *pk0, *pk1, *pv0, *pv1;
    cudaGetSymbolAddress((void**)&compressed, g_compressed);
    cudaGetSymbolAddress((void**)&ct,   g_ct);
    cudaGetSymbolAddress((void**)&gate, g_gate);
    cudaGetSymbolAddress((void**)&up,   g_up);
    cudaGetSymbolAddress((void**)&p0,   g_p0);
    cudaGetSymbolAddress((void**)&p1,   g_p1);
    cudaGetSymbolAddress((void**)&pk0,  g_pk0);
    cudaGetSymbolAddress((void**)&pk1,  g_pk1);
    cudaGetSymbolAddress((void**)&pv0,  g_pv0);
    cudaGetSymbolAddress((void**)&pv1,  g_pv1);

    __nv_bfloat16 *res_hi, *res_lo, *ct_hi, *ct_lo, *ao_hi, *ao_lo, *ga_hi, *ga_lo,
                  *hT_hi, *hT_lo, *q_hi, *q_lo, *k_hi, *k_lo, *v_hi, *v_lo,
                  *cw_hi, *cw_lo, *qw_hi, *qw_lo, *kw_hi, *kw_lo,
                  *vw_hi, *vw_lo, *ow_hi, *ow_lo, *gw_hi, *gw_lo, *uw_hi, *uw_lo,
                  *dw_hi, *dw_lo;
    cudaGetSymbolAddress((void**)&res_hi, g_res_hi); cudaGetSymbolAddress((void**)&res_lo, g_res_lo);
    cudaGetSymbolAddress((void**)&ct_hi,  g_ct_hi);  cudaGetSymbolAddress((void**)&ct_lo,  g_ct_lo);
    cudaGetSymbolAddress((void**)&ao_hi,  g_ao_hi);  cudaGetSymbolAddress((void**)&ao_lo,  g_ao_lo);
    cudaGetSymbolAddress((void**)&ga_hi,  g_ga_hi);  cudaGetSymbolAddress((void**)&ga_lo,  g_ga_lo);
    cudaGetSymbolAddress((void**)&hT_hi,  g_hT_hi);  cudaGetSymbolAddress((void**)&hT_lo,  g_hT_lo);
    cudaGetSymbolAddress((void**)&q_hi,   g_q_hi);   cudaGetSymbolAddress((void**)&q_lo,   g_q_lo);
    cudaGetSymbolAddress((void**)&k_hi,   g_k_hi);   cudaGetSymbolAddress((void**)&k_lo,   g_k_lo);
    cudaGetSymbolAddress((void**)&v_hi,   g_v_hi);   cudaGetSymbolAddress((void**)&v_lo,   g_v_lo);
    cudaGetSymbolAddress((void**)&cw_hi,  g_cw_hi);  cudaGetSymbolAddress((void**)&cw_lo,  g_cw_lo);
    cudaGetSymbolAddress((void**)&qw_hi,  g_qw_hi);  cudaGetSymbolAddress((void**)&qw_lo,  g_qw_lo);
    cudaGetSymbolAddress((void**)&kw_hi,  g_kw_hi);  cudaGetSymbolAddress((void**)&kw_lo,  g_kw_lo);
    cudaGetSymbolAddress((void**)&vw_hi,  g_vw_hi);  cudaGetSymbolAddress((void**)&vw_lo,  g_vw_lo);
    cudaGetSymbolAddress((void**)&ow_hi,  g_ow_hi);  cudaGetSymbolAddress((void**)&ow_lo,  g_ow_lo);
    cudaGetSymbolAddress((void**)&gw_hi,  g_gw_hi);  cudaGetSymbolAddress((void**)&gw_lo,  g_gw_lo);
    cudaGetSymbolAddress((void**)&uw_hi,  g_uw_hi);  cudaGetSymbolAddress((void**)&uw_lo,  g_uw_lo);
    cudaGetSymbolAddress((void**)&dw_hi,  g_dw_hi);  cudaGetSymbolAddress((void**)&dw_lo,  g_dw_lo);

    auto split = [&](const float* src, __nv_bfloat16* hi, __nv_bfloat16* lo, int n) {
        int n4 = n / 4;
        split_kernel<<<(n4 + 1023) / 1024, 256>>>(src, hi, lo, n4);
    };

    split(comp_w, cw_hi, cw_lo, 1024 * 2048);
    split(q_w,    qw_hi, qw_lo, 2048 * 2048);
    split(k_w,    kw_hi, kw_lo, 512 * 2048);
    split(v_w,    vw_hi, vw_lo, 512 * 2048);
    split(o_w,    ow_hi, ow_lo, 2048 * 2048);
    split(gate_w, gw_hi, gw_lo, 5632 * 2048);
    split(up_w,   uw_hi, uw_lo, 5632 * 2048);
    split(down_w, dw_hi, dw_lo, 2048 * 5632);
    transpose_split<<<dim3(64, 64), dim3(32, 8)>>>(hidden, hT_hi, hT_lo, 2048, 2048);
    split(hidden, res_hi, res_lo, 2048 * 2048);

    const int N4 = 1024 * 2048 / 4;
    const int KV4 = 3072 * 512 / 4;

    bgemm_splitk<<<256, 128, SMEM_GEMM>>>(cw_hi, cw_lo, hT_hi, hT_lo,
                                          p0, p1, 2048, 2048, 1024);
    reduce2<1,0,1,1><<<N4 / 1024, 256>>>(p0, p1, comp_b, compressed,
        res_hi + 2048 * 2048, res_lo + 2048 * 2048, N4, 512);

    for (int layer = 0; layer < 2; layer++) {
        rmsnorm_kernel<<<1024, 256>>>(compressed, attn_norm_w, ct, ct_hi, ct_lo);

        bgemm_qkv<<<512, 128, SMEM_GEMM>>>(ct_hi, ct_lo, res_hi, res_lo,
            qw_hi, qw_lo, kw_hi, kw_lo, vw_hi, vw_lo,
            q_hi, q_lo, pk0, pk1, pv0, pv1);
        reduce2<0,0,0,1><<<KV4 / 1024, 256>>>(pk0, pk1, nullptr, nullptr,
                                              k_hi, k_lo, KV4, 0);
        reduce2<0,0,0,1><<<KV4 / 1024, 256>>>(pv0, pv1, nullptr, nullptr,
                                              v_hi, v_lo, KV4, 0);

        attn_mma<<<dim3(16, 32), 128, SMEM_ATTN>>>(q_hi, q_lo, k_hi, k_lo,
                                                   v_hi, v_lo, ao_hi, ao_lo);

        bgemm_splitk<<<256, 128, SMEM_GEMM>>>(ao_hi, ao_lo, ow_hi, ow_lo,
                                              p0, p1, 2048, 2048, 1024);
        reduce2<0,1,1,0><<<N4 / 1024, 256>>>(p0, p1, ct, compressed,
                                             nullptr, nullptr, N4, 0);

        rmsnorm_kernel<<<1024, 256>>>(compressed, mlp_norm_w, ct, ct_hi, ct_lo);

        bgemm_gateup<<<704, 128, SMEM_GEMM>>>(ct_hi, ct_lo, gw_hi, gw_lo,
                                              uw_hi, uw_lo, gate, up);
        swiglu_split<<<(1024 * 5632 + 255) / 256, 256>>>(gate, up, ga_hi, ga_lo,
                                                         1024 * 5632);

        bgemm_splitk<<<256, 128, SMEM_GEMM>>>(ga_hi, ga_lo, dw_hi, dw_lo,
                                              p0, p1, 2048, 5632, 2816);
        if (layer == 0) {
            reduce2<0,1,1,1><<<N4 / 1024, 256>>>(p0, p1, ct, compressed,
                res_hi + 2048 * 2048, res_lo + 2048 * 2048, N4, 0);
        } else {
            reduce2<0,1,1,0><<<N4 / 1024, 256>>>(p0, p1, ct, out,
                                                 nullptr, nullptr, N4, 0);
        }
    }
}

// round 11
// speedup vs baseline: 1.0609x; 1.0609x over previous
#include <cuda_runtime.h>
#include <cuda_bf16.h>
#include <cstdint>
#include <math.h>

// ===========================================================================
// S=2048, H=2048, COMP=1024, T=3072, KV_DIM=512, FF=5632, NH=32, NKV=8,
// HD=64, DEPTH=2. mma.sync.m16n8k16 bf16 hi/lo 3-product split everywhere.
// R10: revert GEMM to R8 (8 warps, 32x64/warp); mega-split kernel (1 launch
//      for all weight conversions); fused K+V reduce.
// ===========================================================================

// -------------------- device-global scratch (no allocs) --------------------
__device__ float g_compressed[1024 * 2048];
__device__ float g_ct[1024 * 2048];
__device__ float g_gate[1024 * 5632];
__device__ float g_up[1024 * 5632];
__device__ float g_p0[1024 * 2048], g_p1[1024 * 2048];
__device__ float g_pk0[3072 * 512], g_pk1[3072 * 512];
__device__ float g_pv0[3072 * 512], g_pv1[3072 * 512];

__device__ __nv_bfloat16 g_res_hi[3072 * 2048], g_res_lo[3072 * 2048];
__device__ __nv_bfloat16 g_ct_hi[1024 * 2048], g_ct_lo[1024 * 2048];
__device__ __nv_bfloat16 g_ao_hi[1024 * 2048], g_ao_lo[1024 * 2048];
__device__ __nv_bfloat16 g_ga_hi[1024 * 5632], g_ga_lo[1024 * 5632];
__device__ __nv_bfloat16 g_hT_hi[2048 * 2048], g_hT_lo[2048 * 2048];

__device__ __nv_bfloat16 g_q_hi[1024 * 2048], g_q_lo[1024 * 2048];
__device__ __nv_bfloat16 g_k_hi[3072 * 512],  g_k_lo[3072 * 512];
__device__ __nv_bfloat16 g_v_hi[3072 * 512],  g_v_lo[3072 * 512];

__device__ __nv_bfloat16 g_cw_hi[1024 * 2048], g_cw_lo[1024 * 2048];
__device__ __nv_bfloat16 g_qw_hi[2048 * 2048], g_qw_lo[2048 * 2048];
__device__ __nv_bfloat16 g_kw_hi[512 * 2048],  g_kw_lo[512 * 2048];
__device__ __nv_bfloat16 g_vw_hi[512 * 2048],  g_vw_lo[512 * 2048];
__device__ __nv_bfloat16 g_ow_hi[2048 * 2048], g_ow_lo[2048 * 2048];
__device__ __nv_bfloat16 g_gw_hi[5632 * 2048], g_gw_lo[5632 * 2048];
__device__ __nv_bfloat16 g_uw_hi[5632 * 2048], g_uw_lo[5632 * 2048];
__device__ __nv_bfloat16 g_dw_hi[2048 * 5632], g_dw_lo[2048 * 5632];

// -------------------- helpers --------------------
__device__ __forceinline__ uint32_t smem_u32(const void* p) {
    return (uint32_t)__cvta_generic_to_shared(p);
}

#define LDSM_X4(r0, r1, r2, r3, addr)                                          \
    asm volatile("ldmatrix.sync.aligned.m8n8.x4.shared.b16 {%0,%1,%2,%3}, [%4];" \
                 : "=r"(r0), "=r"(r1), "=r"(r2), "=r"(r3) : "r"(addr))
#define LDSM_X4_T(r0, r1, r2, r3, addr)                                        \
    asm volatile("ldmatrix.sync.aligned.m8n8.x4.trans.shared.b16 {%0,%1,%2,%3}, [%4];" \
                 : "=r"(r0), "=r"(r1), "=r"(r2), "=r"(r3) : "r"(addr))

#define MMA_BF16(ac, ar, br)                                                   \
    asm volatile(                                                              \
        "mma.sync.aligned.m16n8k16.row.col.f32.bf16.bf16.f32 "                 \
        "{%0,%1,%2,%3},{%4,%5,%6,%7},{%8,%9},{%0,%1,%2,%3};"                   \
        : "+f"((ac)[0]), "+f"((ac)[1]), "+f"((ac)[2]), "+f"((ac)[3])           \
        : "r"((ar)[0]), "r"((ar)[1]), "r"((ar)[2]), "r"((ar)[3]),              \
          "r"((br)[0]), "r"((br)[1]))

#define CP_ASYNC16(dst, src)                                                   \
    asm volatile("cp.async.cg.shared.global [%0], [%1], 16;" :: "r"(dst), "l"(src))
#define CP_COMMIT() asm volatile("cp.async.commit_group;")
#define CP_WAIT1()  asm volatile("cp.async.wait_group 1;")

__device__ __forceinline__ uint32_t pack_bf2(float x, float y) {
    __nv_bfloat162 h = __floats2bfloat162_rn(x, y);
    return *(uint32_t*)&h;
}

// ==================== HMMA split-bf16 GEMM body (R8: 8 warps, 32x64) =======
__device__ __forceinline__ void load_stage(
    uint32_t sb, int kc, int tid, int m0, int n0, int K,
    const __nv_bfloat16* __restrict__ Ahi, const __nv_bfloat16* __restrict__ Alo,
    const __nv_bfloat16* __restrict__ Bhi, const __nv_bfloat16* __restrict__ Blo)
{
    const int kb = kc * 32;
#pragma unroll
    for (int i = 0; i < 2; i++) {
        int f = tid + i * 256;
        int r = f >> 2, c = f & 3;
        uint32_t off = (uint32_t)(r * 64) +
                       (uint32_t)((c * 16) ^ (((r >> 1) & 3) << 4));
        size_t ga = (size_t)(m0 + r) * K + kb + c * 8;
        size_t gb = (size_t)(n0 + r) * K + kb + c * 8;
        CP_ASYNC16(sb + off,         Ahi + ga);
        CP_ASYNC16(sb + 8192 + off,  Alo + ga);
        CP_ASYNC16(sb + 16384 + off, Bhi + gb);
        CP_ASYNC16(sb + 24576 + off, Blo + gb);
    }
}

template <int OUT>
__device__ __forceinline__ void bgemm_body(
    const __nv_bfloat16* __restrict__ Ahi, const __nv_bfloat16* __restrict__ Alo,
    const __nv_bfloat16* __restrict__ Bhi, const __nv_bfloat16* __restrict__ Blo,
    float* __restrict__ C,
    __nv_bfloat16* __restrict__ Chi, __nv_bfloat16* __restrict__ Clo,
    int N, int K, int Klen, int m0, int n0)
{
    extern __shared__ char dsm[];
    const int tid = threadIdx.x;
    const int wid = tid >> 5, lid = tid & 31;
    const int wm = wid & 3, wn = wid >> 2;
    const uint32_t sbase = smem_u32(dsm);

    const int arow = wm * 32 + (lid & 7) + ((lid >> 3) & 1) * 8;
    const uint32_t a_base = (uint32_t)(arow * 64);
    const uint32_t a_sw = (uint32_t)(((arow >> 1) & 3) << 4);
    const uint32_t a_k = (uint32_t)((lid >> 4) & 1) * 16;

    const int brow = wn * 64 + (lid & 7) + ((lid >> 4) & 1) * 8;
    const uint32_t b_base = (uint32_t)(brow * 64);
    const uint32_t b_sw = (uint32_t)(((brow >> 1) & 3) << 4);
    const uint32_t b_k = (uint32_t)((lid >> 3) & 1) * 16;

    float acc[2][8][4];
#pragma unroll
    for (int mt = 0; mt < 2; mt++)
#pragma unroll
        for (int nt = 0; nt < 8; nt++)
#pragma unroll
            for (int e = 0; e < 4; e++) acc[mt][nt][e] = 0.f;

    const int NK = Klen / 32;
    load_stage(sbase, 0, tid, m0, n0, K, Ahi, Alo, Bhi, Blo);
    CP_COMMIT();
    load_stage(sbase + 32768, 1, tid, m0, n0, K, Ahi, Alo, Bhi, Blo);
    CP_COMMIT();

    for (int kc = 0; kc < NK; kc++) {
        CP_WAIT1();
        __syncthreads();
        if (kc + 2 < NK)
            load_stage(sbase + (uint32_t)((kc + 2) % 3) * 32768, kc + 2, tid,
                       m0, n0, K, Ahi, Alo, Bhi, Blo);
        CP_COMMIT();

        const uint32_t st = sbase + (uint32_t)(kc % 3) * 32768;
#pragma unroll
        for (int ks = 0; ks < 2; ks++) {
            const uint32_t ako = (a_k + (uint32_t)ks * 32) ^ a_sw;
            const uint32_t bko = (b_k + (uint32_t)ks * 32) ^ b_sw;
            uint32_t ah[2][4], al[2][4], bb[8][2];
#pragma unroll
            for (int mt = 0; mt < 2; mt++) {
                LDSM_X4(ah[mt][0], ah[mt][1], ah[mt][2], ah[mt][3],
                        st + a_base + (uint32_t)mt * 1024 + ako);
                LDSM_X4(al[mt][0], al[mt][1], al[mt][2], al[mt][3],
                        st + 8192 + a_base + (uint32_t)mt * 1024 + ako);
            }
#pragma unroll
            for (int p = 0; p < 4; p++) {
                LDSM_X4(bb[2*p][0], bb[2*p][1], bb[2*p+1][0], bb[2*p+1][1],
                        st + 16384 + b_base + (uint32_t)p * 1024 + bko);
            }
#pragma unroll
            for (int nt = 0; nt < 8; nt++)
#pragma unroll
                for (int mt = 0; mt < 2; mt++)
                    MMA_BF16(acc[mt][nt], ah[mt], bb[nt]);
#pragma unroll
            for (int nt = 0; nt < 8; nt++)
#pragma unroll
                for (int mt = 0; mt < 2; mt++)
                    MMA_BF16(acc[mt][nt], al[mt], bb[nt]);
#pragma unroll
            for (int p = 0; p < 4; p++) {
                LDSM_X4(bb[2*p][0], bb[2*p][1], bb[2*p+1][0], bb[2*p+1][1],
                        st + 24576 + b_base + (uint32_t)p * 1024 + bko);
            }
#pragma unroll
            for (int nt = 0; nt < 8; nt++)
#pragma unroll
                for (int mt = 0; mt < 2; mt++)
                    MMA_BF16(acc[mt][nt], ah[mt], bb[nt]);
        }
    }

    const int grow0 = m0 + wm * 32 + (lid >> 2);
    const int gcol0 = n0 + wn * 64 + (lid & 3) * 2;
#pragma unroll
    for (int mt = 0; mt < 2; mt++) {
#pragma unroll
        for (int nt = 0; nt < 8; nt++) {
            int r0 = grow0 + mt * 16;
            int c0 = gcol0 + nt * 8;
            float2 v0 = make_float2(acc[mt][nt][0], acc[mt][nt][1]);
            float2 v1 = make_float2(acc[mt][nt][2], acc[mt][nt][3]);
            if (OUT == 0) {
                *(float2*)(C + (size_t)r0 * N + c0) = v0;
                *(float2*)(C + (size_t)(r0 + 8) * N + c0) = v1;
            } else {
                uint32_t h0 = pack_bf2(v0.x, v0.y);
                uint32_t h1 = pack_bf2(v1.x, v1.y);
                *(uint32_t*)(Chi + (size_t)r0 * N + c0) = h0;
                *(uint32_t*)(Chi + (size_t)(r0 + 8) * N + c0) = h1;
                __nv_bfloat162 hh0 = *(__nv_bfloat162*)&h0;
                __nv_bfloat162 hh1 = *(__nv_bfloat162*)&h1;
                *(uint32_t*)(Clo + (size_t)r0 * N + c0) =
                    pack_bf2(v0.x - __bfloat162float(hh0.x),
                             v0.y - __bfloat162float(hh0.y));
                *(uint32_t*)(Clo + (size_t)(r0 + 8) * N + c0) =
                    pack_bf2(v1.x - __bfloat162float(hh1.x),
                             v1.y - __bfloat162float(hh1.y));
            }
        }
    }
}

__global__ __launch_bounds__(256, 2) void bgemm_splitk(
    const __nv_bfloat16* __restrict__ Ahi, const __nv_bfloat16* __restrict__ Alo,
    const __nv_bfloat16* __restrict__ Bhi, const __nv_bfloat16* __restrict__ Blo,
    float* __restrict__ P0, float* __restrict__ P1,
    int N, int K, int Khalf)
{
    const int per = gridDim.x >> 1;
    int id = blockIdx.x;
    const int half = (id >= per) ? 1 : 0;
    if (half) id -= per;
    const int ntn = N >> 7;
    const int m0 = (id / ntn) * 128, n0 = (id % ntn) * 128;
    const int ko = half * Khalf;
    bgemm_body<0>(Ahi + ko, Alo + ko, Bhi + ko, Blo + ko,
                  half ? P1 : P0, nullptr, nullptr, N, K, Khalf, m0, n0);
}

__global__ __launch_bounds__(256, 2) void bgemm_qkv(
    const __nv_bfloat16* __restrict__ ct_hi, const __nv_bfloat16* __restrict__ ct_lo,
    const __nv_bfloat16* __restrict__ res_hi, const __nv_bfloat16* __restrict__ res_lo,
    const __nv_bfloat16* __restrict__ qw_hi, const __nv_bfloat16* __restrict__ qw_lo,
    const __nv_bfloat16* __restrict__ kw_hi, const __nv_bfloat16* __restrict__ kw_lo,
    const __nv_bfloat16* __restrict__ vw_hi, const __nv_bfloat16* __restrict__ vw_lo,
    __nv_bfloat16* __restrict__ q_hi, __nv_bfloat16* __restrict__ q_lo,
    float* __restrict__ pk0, float* __restrict__ pk1,
    float* __restrict__ pv0, float* __restrict__ pv1)
{
    int id = blockIdx.x;
    if (id < 128) {
        bgemm_body<1>(ct_hi, ct_lo, qw_hi, qw_lo, nullptr, q_hi, q_lo,
                      2048, 2048, 2048, (id >> 4) * 128, (id & 15) * 128);
    } else {
        int id2 = id - 128;
        const int part = id2 / 96;
        const int t = id2 % 96;
        const int half = part & 1, isv = part >> 1;
        const int ko = half * 1024;
        const __nv_bfloat16* bh = (isv ? vw_hi : kw_hi) + ko;
        const __nv_bfloat16* bl = (isv ? vw_lo : kw_lo) + ko;
        float* P = isv ? (half ? pv1 : pv0) : (half ? pk1 : pk0);
        bgemm_body<0>(res_hi + ko, res_lo + ko, bh, bl, P, nullptr, nullptr,
                      512, 2048, 1024, (t >> 2) * 128, (t & 3) * 128);
    }
}

__global__ __launch_bounds__(256, 2) void bgemm_gateup(
    const __nv_bfloat16* __restrict__ ct_hi, const __nv_bfloat16* __restrict__ ct_lo,
    const __nv_bfloat16* __restrict__ gw_hi, const __nv_bfloat16* __restrict__ gw_lo,
    const __nv_bfloat16* __restrict__ uw_hi, const __nv_bfloat16* __restrict__ uw_lo,
    float* __restrict__ gate, float* __restrict__ up)
{
    int id = blockIdx.x;
    if (id < 352) {
        bgemm_body<0>(ct_hi, ct_lo, gw_hi, gw_lo, gate, nullptr, nullptr,
                      5632, 2048, 2048, (id / 44) * 128, (id % 44) * 128);
    } else {
        id -= 352;
        bgemm_body<0>(ct_hi, ct_lo, uw_hi, uw_lo, up, nullptr, nullptr,
                      5632, 2048, 2048, (id / 44) * 128, (id % 44) * 128);
    }
}

// ==================== split-K reduce ====================
template <int BIAS, int CT, int OF32, int OSPLIT>
__global__ void reduce2(const float* __restrict__ P0, const float* __restrict__ P1,
                        const float* __restrict__ aux, float* __restrict__ C,
                        __nv_bfloat16* __restrict__ hi, __nv_bfloat16* __restrict__ lo,
                        int n4, int rowdiv)
{
    int i = blockIdx.x * 1024 + threadIdx.x;
#pragma unroll
    for (int u = 0; u < 4; u++, i += 256) {
        if (i < n4) {
            float4 a = ((const float4*)P0)[i];
            float4 b = ((const float4*)P1)[i];
            float4 v = make_float4(a.x + b.x, a.y + b.y, a.z + b.z, a.w + b.w);
            if (BIAS) {
                float bb = aux[i / rowdiv];
                v.x += bb; v.y += bb; v.z += bb; v.w += bb;
            }
            if (CT) {
                float4 c = ((const float4*)aux)[i];
                v.x += c.x; v.y += c.y; v.z += c.z; v.w += c.w;
            }
            if (OF32) ((float4*)C)[i] = v;
            if (OSPLIT) {
                uint32_t h0 = pack_bf2(v.x, v.y), h1 = pack_bf2(v.z, v.w);
                ((uint32_t*)hi)[i * 2]     = h0;
                ((uint32_t*)hi)[i * 2 + 1] = h1;
                __nv_bfloat162 a0 = *(__nv_bfloat162*)&h0;
                __nv_bfloat162 a1 = *(__nv_bfloat162*)&h1;
                ((uint32_t*)lo)[i * 2] =
                    pack_bf2(v.x - __bfloat162float(a0.x), v.y - __bfloat162float(a0.y));
                ((uint32_t*)lo)[i * 2 + 1] =
                    pack_bf2(v.z - __bfloat162float(a1.x), v.w - __bfloat162float(a1.y));
            }
        }
    }
}

// fused K+V reduce (both 3072x512): blocks [0,384) k, [384,768) v
__global__ void reduce_kv(const float* __restrict__ pk0, const float* __restrict__ pk1,
                          const float* __restrict__ pv0, const float* __restrict__ pv1,
                          __nv_bfloat16* __restrict__ k_hi, __nv_bfloat16* __restrict__ k_lo,
                          __nv_bfloat16* __restrict__ v_hi, __nv_bfloat16* __restrict__ v_lo,
                          int n4each)
{
    int blk = blockIdx.x;
    const float *P0, *P1;
    __nv_bfloat16 *hi, *lo;
    int nblk = (n4each + 1023) / 1024;
    if (blk < nblk) { P0 = pk0; P1 = pk1; hi = k_hi; lo = k_lo; }
    else { blk -= nblk; P0 = pv0; P1 = pv1; hi = v_hi; lo = v_lo; }
    int i = blk * 1024 + threadIdx.x;
#pragma unroll
    for (int u = 0; u < 4; u++, i += 256) {
        if (i < n4each) {
            float4 a = ((const float4*)P0)[i];
            float4 b = ((const float4*)P1)[i];
            float4 v = make_float4(a.x + b.x, a.y + b.y, a.z + b.z, a.w + b.w);
            uint32_t h0 = pack_bf2(v.x, v.y), h1 = pack_bf2(v.z, v.w);
            ((uint32_t*)hi)[i * 2]     = h0;
            ((uint32_t*)hi)[i * 2 + 1] = h1;
            __nv_bfloat162 a0 = *(__nv_bfloat162*)&h0;
            __nv_bfloat162 a1 = *(__nv_bfloat162*)&h1;
            ((uint32_t*)lo)[i * 2] =
                pack_bf2(v.x - __bfloat162float(a0.x), v.y - __bfloat162float(a0.y));
            ((uint32_t*)lo)[i * 2 + 1] =
                pack_bf2(v.z - __bfloat162float(a1.x), v.w - __bfloat162float(a1.y));
        }
    }
}

// ==================== mega split: all weight conversions, one launch =======
struct SplitArgs {
    const float* src[9];
    __nv_bfloat16* hi[9];
    __nv_bfloat16* lo[9];
    int blk_start[10];   // block prefix
    int n4[9];
};

__global__ void megasplit_kernel(SplitArgs a)
{
    int blk = blockIdx.x;
    int j = 0;
#pragma unroll
    for (int t = 1; t < 9; t++)
        if (blk >= a.blk_start[t]) j = t;
    const float* src = a.src[j];
    __nv_bfloat16* hi = a.hi[j];
    __nv_bfloat16* lo = a.lo[j];
    const int n4 = a.n4[j];
    int i = (blk - a.blk_start[j]) * 1024 + threadIdx.x;
#pragma unroll
    for (int u = 0; u < 4; u++, i += 256) {
        if (i < n4) {
            float4 v = ((const float4*)src)[i];
            uint32_t h0 = pack_bf2(v.x, v.y), h1 = pack_bf2(v.z, v.w);
            ((uint32_t*)hi)[i * 2]     = h0;
            ((uint32_t*)hi)[i * 2 + 1] = h1;
            __nv_bfloat162 a0 = *(__nv_bfloat162*)&h0;
            __nv_bfloat162 a1 = *(__nv_bfloat162*)&h1;
            ((uint32_t*)lo)[i * 2] =
                pack_bf2(v.x - __bfloat162float(a0.x), v.y - __bfloat162float(a0.y));
            ((uint32_t*)lo)[i * 2 + 1] =
                pack_bf2(v.z - __bfloat162float(a1.x), v.w - __bfloat162float(a1.y));
        }
    }
}

// ==================== HMMA split-bf16 flash attention (R8) =================
__global__ __launch_bounds__(128, 4) void attn_mma(
    const __nv_bfloat16* __restrict__ Qhi, const __nv_bfloat16* __restrict__ Qlo,
    const __nv_bfloat16* __restrict__ Khi, const __nv_bfloat16* __restrict__ Klo,
    const __nv_bfloat16* __restrict__ Vhi, const __nv_bfloat16* __restrict__ Vlo,
    __nv_bfloat16* __restrict__ Ohi, __nv_bfloat16* __restrict__ Olo)
{
    extern __shared__ char sm[];
    const int tid = threadIdx.x;
    const int wid = tid >> 5, lid = tid & 31;
    const int q0 = blockIdx.x * 64;
    const int head = blockIdx.y;
    const int kvoff = (head >> 2) * 64;
    const uint32_t sb = smem_u32(sm);
    const uint32_t sQh = sb, sQl = sb + 8192;
    const uint32_t sKV = sb + 16384;

#pragma unroll
    for (int i = 0; i < 4; i++) {
        int f = tid + i * 128;
        int r = f >> 3, c = f & 7;
        uint32_t off = (uint32_t)(r * 128) + (uint32_t)((c * 16) ^ ((r & 7) << 4));
        size_t g = (size_t)(q0 + r) * 2048 + head * 64 + c * 8;
        CP_ASYNC16(sQh + off, Qhi + g);
        CP_ASYNC16(sQl + off, Qlo + g);
    }
    CP_COMMIT();

#define ISSUE_KV(t0, st)                                                       \
    {                                                                          \
        uint32_t s_ = sKV + (uint32_t)(st) * 16384;                            \
        _Pragma("unroll")                                                      \
        for (int i_ = 0; i_ < 2; i_++) {                                       \
            int f_ = tid + i_ * 128;                                           \
            int r_ = f_ >> 3, c_ = f_ & 7;                                     \
            uint32_t o_ = (uint32_t)(r_ * 128) +                               \
                          (uint32_t)((c_ * 16) ^ ((r_ & 7) << 4));             \
            size_t g_ = (size_t)((t0) + r_) * 512 + kvoff + c_ * 8;            \
            CP_ASYNC16(s_ + o_,         Khi + g_);                             \
            CP_ASYNC16(s_ + 4096 + o_,  Klo + g_);                             \
            CP_ASYNC16(s_ + 8192 + o_,  Vhi + g_);                             \
            CP_ASYNC16(s_ + 12288 + o_, Vlo + g_);                             \
        }                                                                      \
    }

    ISSUE_KV(0, 0);  CP_COMMIT();
    ISSUE_KV(32, 1); CP_COMMIT();

    CP_WAIT1();
    __syncthreads();

    uint32_t qh[4][4], ql[4][4];
    {
        const int ar = (lid & 7) + ((lid >> 3) & 1) * 8;
        const int row = wid * 16 + ar;
        const uint32_t khalf = (uint32_t)((lid >> 4) & 1) * 16;
#pragma unroll
        for (int ks = 0; ks < 4; ks++) {
            uint32_t off = (uint32_t)(row * 128) +
                           ((khalf + (uint32_t)ks * 32) ^ ((uint32_t)(ar & 7) << 4));
            LDSM_X4(qh[ks][0], qh[ks][1], qh[ks][2], qh[ks][3], sQh + off);
            LDSM_X4(ql[ks][0], ql[ks][1], ql[ks][2], ql[ks][3], sQl + off);
        }
    }

    float acc_o[8][4];
#pragma unroll
    for (int d = 0; d < 8; d++)
#pragma unroll
        for (int e = 0; e < 4; e++) acc_o[d][e] = 0.f;
    float mr0 = -1e30f, mr1 = -1e30f, lr0 = 0.f, lr1 = 0.f;

    const int brS = (lid & 7) + ((lid >> 4) & 1) * 8;
    const uint32_t bkS = (uint32_t)((lid >> 3) & 1) * 16;
    const int trV = (lid & 7) + ((lid >> 3) & 1) * 8;
    const uint32_t dkV = (uint32_t)((lid >> 4) & 1) * 16;

    for (int t = 0; t < 96; t++) {
        const uint32_t st = sKV + (uint32_t)(t & 1) * 16384;

        float s[4][4];
#pragma unroll
        for (int nt = 0; nt < 4; nt++)
#pragma unroll
            for (int e = 0; e < 4; e++) s[nt][e] = 0.f;
#pragma unroll
        for (int ks = 0; ks < 4; ks++) {
            uint32_t bh[4][2], bl[4][2];
#pragma unroll
            for (int p = 0; p < 2; p++) {
                int rr = p * 16 + brS;
                uint32_t off = (uint32_t)(rr * 128) +
                               ((bkS + (uint32_t)ks * 32) ^ ((uint32_t)(rr & 7) << 4));
                LDSM_X4(bh[2*p][0], bh[2*p][1], bh[2*p+1][0], bh[2*p+1][1], st + off);
                LDSM_X4(bl[2*p][0], bl[2*p][1], bl[2*p+1][0], bl[2*p+1][1], st + 4096 + off);
            }
#pragma unroll
            for (int nt = 0; nt < 4; nt++) {
                MMA_BF16(s[nt], qh[ks], bh[nt]);
                MMA_BF16(s[nt], qh[ks], bl[nt]);
                MMA_BF16(s[nt], ql[ks], bh[nt]);
            }
        }

        float mn0 = mr0, mn1 = mr1;
#pragma unroll
        for (int nt = 0; nt < 4; nt++) {
            s[nt][0] *= 0.125f; s[nt][1] *= 0.125f;
            s[nt][2] *= 0.125f; s[nt][3] *= 0.125f;
            mn0 = fmaxf(mn0, fmaxf(s[nt][0], s[nt][1]));
            mn1 = fmaxf(mn1, fmaxf(s[nt][2], s[nt][3]));
        }
        mn0 = fmaxf(mn0, __shfl_xor_sync(0xffffffffu, mn0, 1));
        mn0 = fmaxf(mn0, __shfl_xor_sync(0xffffffffu, mn0, 2));
        mn1 = fmaxf(mn1, __shfl_xor_sync(0xffffffffu, mn1, 1));
        mn1 = fmaxf(mn1, __shfl_xor_sync(0xffffffffu, mn1, 2));
        float f0 = __expf(mr0 - mn0), f1 = __expf(mr1 - mn1);
        mr0 = mn0; mr1 = mn1;
        float ps0 = 0.f, ps1 = 0.f;
#pragma unroll
        for (int nt = 0; nt < 4; nt++) {
            s[nt][0] = __expf(s[nt][0] - mn0);
            s[nt][1] = __expf(s[nt][1] - mn0);
            s[nt][2] = __expf(s[nt][2] - mn1);
            s[nt][3] = __expf(s[nt][3] - mn1);
            ps0 += s[nt][0] + s[nt][1];
            ps1 += s[nt][2] + s[nt][3];
        }
        lr0 = lr0 * f0 + ps0;
        lr1 = lr1 * f1 + ps1;
#pragma unroll
        for (int d = 0; d < 8; d++) {
            acc_o[d][0] *= f0; acc_o[d][1] *= f0;
            acc_o[d][2] *= f1; acc_o[d][3] *= f1;
        }

#pragma unroll
        for (int j = 0; j < 2; j++) {
            uint32_t ah[4], al[4];
            {
                float p00 = s[2*j][0],   p01 = s[2*j][1];
                float p02 = s[2*j][2],   p03 = s[2*j][3];
                float p10 = s[2*j+1][0], p11 = s[2*j+1][1];
                float p12 = s[2*j+1][2], p13 = s[2*j+1][3];
                ah[0] = pack_bf2(p00, p01); ah[1] = pack_bf2(p02, p03);
                ah[2] = pack_bf2(p10, p11); ah[3] = pack_bf2(p12, p13);
#pragma unroll
                for (int e = 0; e < 4; e++) {
                    __nv_bfloat162 hh = *(__nv_bfloat162*)&ah[e];
                    float x0, x1;
                    if (e == 0) { x0 = p00; x1 = p01; }
                    else if (e == 1) { x0 = p02; x1 = p03; }
                    else if (e == 2) { x0 = p10; x1 = p11; }
                    else { x0 = p12; x1 = p13; }
                    al[e] = pack_bf2(x0 - __bfloat162float(hh.x),
                                     x1 - __bfloat162float(hh.y));
                }
            }
            const int rr = j * 16 + trV;
#pragma unroll
            for (int dp = 0; dp < 4; dp++) {
                uint32_t off = (uint32_t)(rr * 128) +
                               ((dkV + (uint32_t)dp * 32) ^ ((uint32_t)(rr & 7) << 4));
                uint32_t vh[4], vl[4];
                LDSM_X4_T(vh[0], vh[1], vh[2], vh[3], st + 8192 + off);
                LDSM_X4_T(vl[0], vl[1], vl[2], vl[3], st + 12288 + off);
                uint32_t b0h[2] = {vh[0], vh[1]}, b1h[2] = {vh[2], vh[3]};
                uint32_t b0l[2] = {vl[0], vl[1]}, b1l[2] = {vl[2], vl[3]};
                MMA_BF16(acc_o[2*dp],   ah, b0h);
                MMA_BF16(acc_o[2*dp],   ah, b0l);
                MMA_BF16(acc_o[2*dp],   al, b0h);
                MMA_BF16(acc_o[2*dp+1], ah, b1h);
                MMA_BF16(acc_o[2*dp+1], ah, b1l);
                MMA_BF16(acc_o[2*dp+1], al, b1h);
            }
        }

        __syncthreads();
        if (t + 2 < 96) ISSUE_KV((t + 2) * 32, t & 1);
        CP_COMMIT();
        if (t + 1 < 96) { CP_WAIT1(); __syncthreads(); }
    }

    lr0 += __shfl_xor_sync(0xffffffffu, lr0, 1);
    lr0 += __shfl_xor_sync(0xffffffffu, lr0, 2);
    lr1 += __shfl_xor_sync(0xffffffffu, lr1, 1);
    lr1 += __shfl_xor_sync(0xffffffffu, lr1, 2);
    float il0 = 1.f / lr0, il1 = 1.f / lr1;
    const int row0 = q0 + wid * 16 + (lid >> 2);
    const int col0 = head * 64 + (lid & 3) * 2;
#pragma unroll
    for (int d = 0; d < 8; d++) {
        int col = col0 + d * 8;
        float o0 = acc_o[d][0] * il0, o1 = acc_o[d][1] * il0;
        float o2 = acc_o[d][2] * il1, o3 = acc_o[d][3] * il1;
        uint32_t h0 = pack_bf2(o0, o1), h1 = pack_bf2(o2, o3);
        *(uint32_t*)(Ohi + (size_t)row0 * 2048 + col) = h0;
        *(uint32_t*)(Ohi + (size_t)(row0 + 8) * 2048 + col) = h1;
        __nv_bfloat162 hh0 = *(__nv_bfloat162*)&h0;
        __nv_bfloat162 hh1 = *(__nv_bfloat162*)&h1;
        *(uint32_t*)(Olo + (size_t)row0 * 2048 + col) =
            pack_bf2(o0 - __bfloat162float(hh0.x), o1 - __bfloat162float(hh0.y));
        *(uint32_t*)(Olo + (size_t)(row0 + 8) * 2048 + col) =
            pack_bf2(o2 - __bfloat162float(hh1.x), o3 - __bfloat162float(hh1.y));
    }
}

// -------------------- misc elementwise --------------------
__global__ void transpose_split(const float* __restrict__ x,
                                __nv_bfloat16* __restrict__ hiT,
                                __nv_bfloat16* __restrict__ loT, int R, int C)
{
    __shared__ float t[32][33];
    int c0 = blockIdx.x * 32, r0 = blockIdx.y * 32;
    for (int i = threadIdx.y; i < 32; i += 8)
        t[i][threadIdx.x] = x[(size_t)(r0 + i) * C + c0 + threadIdx.x];
    __syncthreads();
    for (int i = threadIdx.y; i < 32; i += 8) {
        float v = t[threadIdx.x][i];
        __nv_bfloat16 h = __float2bfloat16(v);
        size_t o = (size_t)(c0 + i) * R + r0 + threadIdx.x;
        hiT[o] = h;
        loT[o] = __float2bfloat16(v - __bfloat162float(h));
    }
}

__global__ void rmsnorm_kernel(const float* __restrict__ x,
                               const float* __restrict__ w,
                               float* __restrict__ y,
                               __nv_bfloat16* __restrict__ yhi,
                               __nv_bfloat16* __restrict__ ylo)
{
    const int row = blockIdx.x;
    const float* xr = x + (size_t)row * 2048;
    float ss = 0.f;
    for (int i = threadIdx.x; i < 2048; i += 256) { float v = xr[i]; ss += v * v; }
    __shared__ float red[256];
    red[threadIdx.x] = ss;
    __syncthreads();
    for (int s = 128; s > 0; s >>= 1) {
        if (threadIdx.x < s) red[threadIdx.x] += red[threadIdx.x + s];
        __syncthreads();
    }
    __shared__ float inv;
    if (threadIdx.x == 0) inv = rsqrtf(red[0] * (1.f / 2048.f) + 1e-6f);
    __syncthreads();
    float iv = inv;
    for (int i = threadIdx.x; i < 2048; i += 256) {
        float v = xr[i] * iv * w[i];
        size_t o = (size_t)row * 2048 + i;
        y[o] = v;
        __nv_bfloat16 h = __float2bfloat16(v);
        yhi[o] = h;
        ylo[o] = __float2bfloat16(v - __bfloat162float(h));
    }
}

__global__ void swiglu_split(const float* __restrict__ g, const float* __restrict__ u,
                             __nv_bfloat16* __restrict__ hi, __nv_bfloat16* __restrict__ lo,
                             int n)
{
    int i = blockIdx.x * blockDim.x + threadIdx.x;
    if (i < n) {
        float x = g[i];
        float v = (x / (1.f + __expf(-x))) * u[i];
        __nv_bfloat16 h = __float2bfloat16(v);
        hi[i] = h;
        lo[i] = __float2bfloat16(v - __bfloat162float(h));
    }
}

// -------------------- orchestration --------------------
static const int SMEM_GEMM = 3 * 32768;          // 96KB
static const int SMEM_ATTN = 16384 + 2 * 16384;  // 48KB

extern "C" void kernel_launch(void* const* d_in, const int* in_sizes, int n_in,
                              void* d_out, int out_size)
{
    (void)in_sizes; (void)n_in; (void)out_size;
    const float* hidden      = (const float*)d_in[0];
    const float* comp_w      = (const float*)d_in[1];
    const float* comp_b      = (const float*)d_in[2];
    const float* q_w         = (const float*)d_in[3];
    const float* k_w         = (const float*)d_in[4];
    const float* v_w         = (const float*)d_in[5];
    const float* o_w         = (const float*)d_in[6];
    const float* attn_norm_w = (const float*)d_in[7];
    const float* mlp_norm_w  = (const float*)d_in[8];
    const float* gate_w      = (const float*)d_in[9];
    const float* up_w        = (const float*)d_in[10];
    const float* down_w      = (const float*)d_in[11];
    float* out = (float*)d_out;

    cudaFuncSetAttribute(bgemm_splitk, cudaFuncAttributeMaxDynamicSharedMemorySize, SMEM_GEMM);
    cudaFuncSetAttribute(bgemm_qkv,    cudaFuncAttributeMaxDynamicSharedMemorySize, SMEM_GEMM);
    cudaFuncSetAttribute(bgemm_gateup, cudaFuncAttributeMaxDynamicSharedMemorySize, SMEM_GEMM);
    cudaFuncSetAttribute(attn_mma,     cudaFuncAttributeMaxDynamicSharedMemorySize, SMEM_ATTN);

    float *compressed, *ct, *gate, *up, *p0, *p1, *pk0, *pk1, *pv0, *pv1;
    cudaGetSymbolAddress((void**)&compressed, g_compressed);
    cudaGetSymbolAddress((void**)&ct,   g_ct);
    cudaGetSymbolAddress((void**)&gate, g_gate);
    cudaGetSymbolAddress((void**)&up,   g_up);
    cudaGetSymbolAddress((void**)&p0,   g_p0);
    cudaGetSymbolAddress((void**)&p1,   g_p1);
    cudaGetSymbolAddress((void**)&pk0,  g_pk0);
    cudaGetSymbolAddress((void**)&pk1,  g_pk1);
    cudaGetSymbolAddress((void**)&pv0,  g_pv0);
    cudaGetSymbolAddress((void**)&pv1,  g_pv1);

    __nv_bfloat16 *res_hi, *res_lo, *ct_hi, *ct_lo, *ao_hi, *ao_lo, *ga_hi, *ga_lo,
                  *hT_hi, *hT_lo, *q_hi, *q_lo, *k_hi, *k_lo, *v_hi, *v_lo,
                  *cw_hi, *cw_lo, *qw_hi, *qw_lo, *kw_hi, *kw_lo,
                  *vw_hi, *vw_lo, *ow_hi, *ow_lo, *gw_hi, *gw_lo, *uw_hi, *uw_lo,
                  *dw_hi, *dw_lo;
    cudaGetSymbolAddress((void**)&res_hi, g_res_hi); cudaGetSymbolAddress((void**)&res_lo, g_res_lo);
    cudaGetSymbolAddress((void**)&ct_hi,  g_ct_hi);  cudaGetSymbolAddress((void**)&ct_lo,  g_ct_lo);
    cudaGetSymbolAddress((void**)&ao_hi,  g_ao_hi);  cudaGetSymbolAddress((void**)&ao_lo,  g_ao_lo);
    cudaGetSymbolAddress((void**)&ga_hi,  g_ga_hi);  cudaGetSymbolAddress((void**)&ga_lo,  g_ga_lo);
    cudaGetSymbolAddress((void**)&hT_hi,  g_hT_hi);  cudaGetSymbolAddress((void**)&hT_lo,  g_hT_lo);
    cudaGetSymbolAddress((void**)&q_hi,   g_q_hi);   cudaGetSymbolAddress((void**)&q_lo,   g_q_lo);
    cudaGetSymbolAddress((void**)&k_hi,   g_k_hi);   cudaGetSymbolAddress((void**)&k_lo,   g_k_lo);
    cudaGetSymbolAddress((void**)&v_hi,   g_v_hi);   cudaGetSymbolAddress((void**)&v_lo,   g_v_lo);
    cudaGetSymbolAddress((void**)&cw_hi,  g_cw_hi);  cudaGetSymbolAddress((void**)&cw_lo,  g_cw_lo);
    cudaGetSymbolAddress((void**)&qw_hi,  g_qw_hi);  cudaGetSymbolAddress((void**)&qw_lo,  g_qw_lo);
    cudaGetSymbolAddress((void**)&kw_hi,  g_kw_hi);  cudaGetSymbolAddress((void**)&kw_lo,  g_kw_lo);
    cudaGetSymbolAddress((void**)&vw_hi,  g_vw_hi);  cudaGetSymbolAddress((void**)&vw_lo,  g_vw_lo);
    cudaGetSymbolAddress((void**)&ow_hi,  g_ow_hi);  cudaGetSymbolAddress((void**)&ow_lo,  g_ow_lo);
    cudaGetSymbolAddress((void**)&gw_hi,  g_gw_hi);  cudaGetSymbolAddress((void**)&gw_lo,  g_gw_lo);
    cudaGetSymbolAddress((void**)&uw_hi,  g_uw_hi);  cudaGetSymbolAddress((void**)&uw_lo,  g_uw_lo);
    cudaGetSymbolAddress((void**)&dw_hi,  g_dw_hi);  cudaGetSymbolAddress((void**)&dw_lo,  g_dw_lo);

    // ---- one mega-split launch for all conversions (8 weights + hidden) ----
    {
        SplitArgs a;
        const float* srcs[9] = {comp_w, q_w, k_w, v_w, o_w, gate_w, up_w, down_w, hidden};
        __nv_bfloat16* his[9] = {cw_hi, qw_hi, kw_hi, vw_hi, ow_hi, gw_hi, uw_hi, dw_hi, res_hi};
        __nv_bfloat16* los[9] = {cw_lo, qw_lo, kw_lo, vw_lo, ow_lo, gw_lo, uw_lo, dw_lo, res_lo};
        int ns[9] = {1024*2048, 2048*2048, 512*2048, 512*2048, 2048*2048,
                     5632*2048, 5632*2048, 2048*5632, 2048*2048};
        int blk = 0;
        for (int j = 0; j < 9; j++) {
            a.src[j] = srcs[j]; a.hi[j] = his[j]; a.lo[j] = los[j];
            a.n4[j] = ns[j] / 4;
            a.blk_start[j] = blk;
            blk += (a.n4[j] + 1023) / 1024;
        }
        a.blk_start[9] = blk;
        megasplit_kernel<<<blk, 256>>>(a);
    }
    transpose_split<<<dim3(64, 64), dim3(32, 8)>>>(hidden, hT_hi, hT_lo, 2048, 2048);

    const int N4 = 1024 * 2048 / 4;
    const int KV4 = 3072 * 512 / 4;

    bgemm_splitk<<<256, 256, SMEM_GEMM>>>(cw_hi, cw_lo, hT_hi, hT_lo,
                                          p0, p1, 2048, 2048, 1024);
    reduce2<1,0,1,1><<<N4 / 1024, 256>>>(p0, p1, comp_b, compressed,
        res_hi + 2048 * 2048, res_lo + 2048 * 2048, N4, 512);

    for (int layer = 0; layer < 2; layer++) {
        rmsnorm_kernel<<<1024, 256>>>(compressed, attn_norm_w, ct, ct_hi, ct_lo);

        bgemm_qkv<<<512, 256, SMEM_GEMM>>>(ct_hi, ct_lo, res_hi, res_lo,
            qw_hi, qw_lo, kw_hi, kw_lo, vw_hi, vw_lo,
            q_hi, q_lo, pk0, pk1, pv0, pv1);
        reduce_kv<<<2 * (KV4 / 1024), 256>>>(pk0, pk1, pv0, pv1,
                                             k_hi, k_lo, v_hi, v_lo, KV4);

        attn_mma<<<dim3(16, 32), 128, SMEM_ATTN>>>(q_hi, q_lo, k_hi, k_lo,
                                                   v_hi, v_lo, ao_hi, ao_lo);

        bgemm_splitk<<<256, 256, SMEM_GEMM>>>(ao_hi, ao_lo, ow_hi, ow_lo,
                                              p0, p1, 2048, 2048, 1024);
        reduce2<0,1,1,0><<<N4 / 1024, 256>>>(p0, p1, ct, compressed,
                                             nullptr, nullptr, N4, 0);

        rmsnorm_kernel<<<1024, 256>>>(compressed, mlp_norm_w, ct, ct_hi, ct_lo);

        bgemm_gateup<<<704, 256, SMEM_GEMM>>>(ct_hi, ct_lo, gw_hi, gw_lo,
                                              uw_hi, uw_lo, gate, up);
        swiglu_split<<<(1024 * 5632 + 255) / 256, 256>>>(gate, up, ga_hi, ga_lo,
                                                         1024 * 5632);

        bgemm_splitk<<<256, 256, SMEM_GEMM>>>(ga_hi, ga_lo, dw_hi, dw_lo,
                                              p0, p1, 2048, 5632, 2816);
        if (layer == 0) {
            reduce2<0,1,1,1><<<N4 / 1024, 256>>>(p0, p1, ct, compressed,
                res_hi + 2048 * 2048, res_lo + 2048 * 2048, N4, 0);
        } else {
            reduce2<0,1,1,0><<<N4 / 1024, 256>>>(p0, p1, ct, out,
                                                 nullptr, nullptr, N4, 0);
        }
    }
}

// round 12
// speedup vs baseline: 1.0770x; 1.0151x over previous
#include <cuda_runtime.h>
#include <cuda_bf16.h>
#include <cstdint>
#include <math.h>

// ===========================================================================
// S=2048, H=2048, COMP=1024, T=3072, KV_DIM=512, FF=5632, NH=32, NKV=8,
// HD=64, DEPTH=2. mma.sync.m16n8k16 bf16 hi/lo 3-product split everywhere.
// R11: wave-smoothed gateup (520 full + 184 split-K tiles = 888 CTAs = 3 full
//      waves); fused reduce+residual+rmsnorm+split kernel (no 'compressed').
// ===========================================================================

// -------------------- device-global scratch (no allocs) --------------------
__device__ float g_ct[1024 * 2048];
__device__ float g_gate[1024 * 5632];
__device__ float g_up[1024 * 5632];
__device__ float g_p0[1024 * 2048], g_p1[1024 * 2048];
__device__ float g_pk0[3072 * 512], g_pk1[3072 * 512];
__device__ float g_pv0[3072 * 512], g_pv1[3072 * 512];
__device__ float g_pg0[184 * 16384], g_pg1[184 * 16384];   // gateup split tiles

__device__ __nv_bfloat16 g_res_hi[3072 * 2048], g_res_lo[3072 * 2048];
__device__ __nv_bfloat16 g_ct_hi[1024 * 2048], g_ct_lo[1024 * 2048];
__device__ __nv_bfloat16 g_ao_hi[1024 * 2048], g_ao_lo[1024 * 2048];
__device__ __nv_bfloat16 g_ga_hi[1024 * 5632], g_ga_lo[1024 * 5632];
__device__ __nv_bfloat16 g_hT_hi[2048 * 2048], g_hT_lo[2048 * 2048];

__device__ __nv_bfloat16 g_q_hi[1024 * 2048], g_q_lo[1024 * 2048];
__device__ __nv_bfloat16 g_k_hi[3072 * 512],  g_k_lo[3072 * 512];
__device__ __nv_bfloat16 g_v_hi[3072 * 512],  g_v_lo[3072 * 512];

__device__ __nv_bfloat16 g_cw_hi[1024 * 2048], g_cw_lo[1024 * 2048];
__device__ __nv_bfloat16 g_qw_hi[2048 * 2048], g_qw_lo[2048 * 2048];
__device__ __nv_bfloat16 g_kw_hi[512 * 2048],  g_kw_lo[512 * 2048];
__device__ __nv_bfloat16 g_vw_hi[512 * 2048],  g_vw_lo[512 * 2048];
__device__ __nv_bfloat16 g_ow_hi[2048 * 2048], g_ow_lo[2048 * 2048];
__device__ __nv_bfloat16 g_gw_hi[5632 * 2048], g_gw_lo[5632 * 2048];
__device__ __nv_bfloat16 g_uw_hi[5632 * 2048], g_uw_lo[5632 * 2048];
__device__ __nv_bfloat16 g_dw_hi[2048 * 5632], g_dw_lo[2048 * 5632];

// -------------------- helpers --------------------
__device__ __forceinline__ uint32_t smem_u32(const void* p) {
    return (uint32_t)__cvta_generic_to_shared(p);
}

#define LDSM_X4(r0, r1, r2, r3, addr)                                          \
    asm volatile("ldmatrix.sync.aligned.m8n8.x4.shared.b16 {%0,%1,%2,%3}, [%4];" \
                 : "=r"(r0), "=r"(r1), "=r"(r2), "=r"(r3) : "r"(addr))
#define LDSM_X4_T(r0, r1, r2, r3, addr)                                        \
    asm volatile("ldmatrix.sync.aligned.m8n8.x4.trans.shared.b16 {%0,%1,%2,%3}, [%4];" \
                 : "=r"(r0), "=r"(r1), "=r"(r2), "=r"(r3) : "r"(addr))

#define MMA_BF16(ac, ar, br)                                                   \
    asm volatile(                                                              \
        "mma.sync.aligned.m16n8k16.row.col.f32.bf16.bf16.f32 "                 \
        "{%0,%1,%2,%3},{%4,%5,%6,%7},{%8,%9},{%0,%1,%2,%3};"                   \
        : "+f"((ac)[0]), "+f"((ac)[1]), "+f"((ac)[2]), "+f"((ac)[3])           \
        : "r"((ar)[0]), "r"((ar)[1]), "r"((ar)[2]), "r"((ar)[3]),              \
          "r"((br)[0]), "r"((br)[1]))

#define CP_ASYNC16(dst, src)                                                   \
    asm volatile("cp.async.cg.shared.global [%0], [%1], 16;" :: "r"(dst), "l"(src))
#define CP_COMMIT() asm volatile("cp.async.commit_group;")
#define CP_WAIT1()  asm volatile("cp.async.wait_group 1;")

__device__ __forceinline__ uint32_t pack_bf2(float x, float y) {
    __nv_bfloat162 h = __floats2bfloat162_rn(x, y);
    return *(uint32_t*)&h;
}

// ==================== HMMA split-bf16 GEMM body (8 warps, 32x64) ===========
__device__ __forceinline__ void load_stage(
    uint32_t sb, int kc, int tid, int m0, int n0, int K,
    const __nv_bfloat16* __restrict__ Ahi, const __nv_bfloat16* __restrict__ Alo,
    const __nv_bfloat16* __restrict__ Bhi, const __nv_bfloat16* __restrict__ Blo)
{
    const int kb = kc * 32;
#pragma unroll
    for (int i = 0; i < 2; i++) {
        int f = tid + i * 256;
        int r = f >> 2, c = f & 3;
        uint32_t off = (uint32_t)(r * 64) +
                       (uint32_t)((c * 16) ^ (((r >> 1) & 3) << 4));
        size_t ga = (size_t)(m0 + r) * K + kb + c * 8;
        size_t gb = (size_t)(n0 + r) * K + kb + c * 8;
        CP_ASYNC16(sb + off,         Ahi + ga);
        CP_ASYNC16(sb + 8192 + off,  Alo + ga);
        CP_ASYNC16(sb + 16384 + off, Bhi + gb);
        CP_ASYNC16(sb + 24576 + off, Blo + gb);
    }
}

template <int OUT>
__device__ __forceinline__ void bgemm_body(
    const __nv_bfloat16* __restrict__ Ahi, const __nv_bfloat16* __restrict__ Alo,
    const __nv_bfloat16* __restrict__ Bhi, const __nv_bfloat16* __restrict__ Blo,
    float* __restrict__ C,
    __nv_bfloat16* __restrict__ Chi, __nv_bfloat16* __restrict__ Clo,
    int N, int K, int Klen, int m0, int n0)
{
    extern __shared__ char dsm[];
    const int tid = threadIdx.x;
    const int wid = tid >> 5, lid = tid & 31;
    const int wm = wid & 3, wn = wid >> 2;
    const uint32_t sbase = smem_u32(dsm);

    const int arow = wm * 32 + (lid & 7) + ((lid >> 3) & 1) * 8;
    const uint32_t a_base = (uint32_t)(arow * 64);
    const uint32_t a_sw = (uint32_t)(((arow >> 1) & 3) << 4);
    const uint32_t a_k = (uint32_t)((lid >> 4) & 1) * 16;

    const int brow = wn * 64 + (lid & 7) + ((lid >> 4) & 1) * 8;
    const uint32_t b_base = (uint32_t)(brow * 64);
    const uint32_t b_sw = (uint32_t)(((brow >> 1) & 3) << 4);
    const uint32_t b_k = (uint32_t)((lid >> 3) & 1) * 16;

    float acc[2][8][4];
#pragma unroll
    for (int mt = 0; mt < 2; mt++)
#pragma unroll
        for (int nt = 0; nt < 8; nt++)
#pragma unroll
            for (int e = 0; e < 4; e++) acc[mt][nt][e] = 0.f;

    const int NK = Klen / 32;
    load_stage(sbase, 0, tid, m0, n0, K, Ahi, Alo, Bhi, Blo);
    CP_COMMIT();
    load_stage(sbase + 32768, 1, tid, m0, n0, K, Ahi, Alo, Bhi, Blo);
    CP_COMMIT();

    for (int kc = 0; kc < NK; kc++) {
        CP_WAIT1();
        __syncthreads();
        if (kc + 2 < NK)
            load_stage(sbase + (uint32_t)((kc + 2) % 3) * 32768, kc + 2, tid,
                       m0, n0, K, Ahi, Alo, Bhi, Blo);
        CP_COMMIT();

        const uint32_t st = sbase + (uint32_t)(kc % 3) * 32768;
#pragma unroll
        for (int ks = 0; ks < 2; ks++) {
            const uint32_t ako = (a_k + (uint32_t)ks * 32) ^ a_sw;
            const uint32_t bko = (b_k + (uint32_t)ks * 32) ^ b_sw;
            uint32_t ah[2][4], al[2][4], bb[8][2];
#pragma unroll
            for (int mt = 0; mt < 2; mt++) {
                LDSM_X4(ah[mt][0], ah[mt][1], ah[mt][2], ah[mt][3],
                        st + a_base + (uint32_t)mt * 1024 + ako);
                LDSM_X4(al[mt][0], al[mt][1], al[mt][2], al[mt][3],
                        st + 8192 + a_base + (uint32_t)mt * 1024 + ako);
            }
#pragma unroll
            for (int p = 0; p < 4; p++) {
                LDSM_X4(bb[2*p][0], bb[2*p][1], bb[2*p+1][0], bb[2*p+1][1],
                        st + 16384 + b_base + (uint32_t)p * 1024 + bko);
            }
#pragma unroll
            for (int nt = 0; nt < 8; nt++)
#pragma unroll
                for (int mt = 0; mt < 2; mt++)
                    MMA_BF16(acc[mt][nt], ah[mt], bb[nt]);
#pragma unroll
            for (int nt = 0; nt < 8; nt++)
#pragma unroll
                for (int mt = 0; mt < 2; mt++)
                    MMA_BF16(acc[mt][nt], al[mt], bb[nt]);
#pragma unroll
            for (int p = 0; p < 4; p++) {
                LDSM_X4(bb[2*p][0], bb[2*p][1], bb[2*p+1][0], bb[2*p+1][1],
                        st + 24576 + b_base + (uint32_t)p * 1024 + bko);
            }
#pragma unroll
            for (int nt = 0; nt < 8; nt++)
#pragma unroll
                for (int mt = 0; mt < 2; mt++)
                    MMA_BF16(acc[mt][nt], ah[mt], bb[nt]);
        }
    }

    const int grow0 = m0 + wm * 32 + (lid >> 2);
    const int gcol0 = n0 + wn * 64 + (lid & 3) * 2;
#pragma unroll
    for (int mt = 0; mt < 2; mt++) {
#pragma unroll
        for (int nt = 0; nt < 8; nt++) {
            int r0 = grow0 + mt * 16;
            int c0 = gcol0 + nt * 8;
            float2 v0 = make_float2(acc[mt][nt][0], acc[mt][nt][1]);
            float2 v1 = make_float2(acc[mt][nt][2], acc[mt][nt][3]);
            if (OUT == 0) {
                *(float2*)(C + (size_t)r0 * N + c0) = v0;
                *(float2*)(C + (size_t)(r0 + 8) * N + c0) = v1;
            } else {
                uint32_t h0 = pack_bf2(v0.x, v0.y);
                uint32_t h1 = pack_bf2(v1.x, v1.y);
                *(uint32_t*)(Chi + (size_t)r0 * N + c0) = h0;
                *(uint32_t*)(Chi + (size_t)(r0 + 8) * N + c0) = h1;
                __nv_bfloat162 hh0 = *(__nv_bfloat162*)&h0;
                __nv_bfloat162 hh1 = *(__nv_bfloat162*)&h1;
                *(uint32_t*)(Clo + (size_t)r0 * N + c0) =
                    pack_bf2(v0.x - __bfloat162float(hh0.x),
                             v0.y - __bfloat162float(hh0.y));
                *(uint32_t*)(Clo + (size_t)(r0 + 8) * N + c0) =
                    pack_bf2(v1.x - __bfloat162float(hh1.x),
                             v1.y - __bfloat162float(hh1.y));
            }
        }
    }
}

__global__ __launch_bounds__(256, 2) void bgemm_splitk(
    const __nv_bfloat16* __restrict__ Ahi, const __nv_bfloat16* __restrict__ Alo,
    const __nv_bfloat16* __restrict__ Bhi, const __nv_bfloat16* __restrict__ Blo,
    float* __restrict__ P0, float* __restrict__ P1,
    int N, int K, int Khalf)
{
    const int per = gridDim.x >> 1;
    int id = blockIdx.x;
    const int half = (id >= per) ? 1 : 0;
    if (half) id -= per;
    const int ntn = N >> 7;
    const int m0 = (id / ntn) * 128, n0 = (id % ntn) * 128;
    const int ko = half * Khalf;
    bgemm_body<0>(Ahi + ko, Alo + ko, Bhi + ko, Blo + ko,
                  half ? P1 : P0, nullptr, nullptr, N, K, Khalf, m0, n0);
}

__global__ __launch_bounds__(256, 2) void bgemm_qkv(
    const __nv_bfloat16* __restrict__ ct_hi, const __nv_bfloat16* __restrict__ ct_lo,
    const __nv_bfloat16* __restrict__ res_hi, const __nv_bfloat16* __restrict__ res_lo,
    const __nv_bfloat16* __restrict__ qw_hi, const __nv_bfloat16* __restrict__ qw_lo,
    const __nv_bfloat16* __restrict__ kw_hi, const __nv_bfloat16* __restrict__ kw_lo,
    const __nv_bfloat16* __restrict__ vw_hi, const __nv_bfloat16* __restrict__ vw_lo,
    __nv_bfloat16* __restrict__ q_hi, __nv_bfloat16* __restrict__ q_lo,
    float* __restrict__ pk0, float* __restrict__ pk1,
    float* __restrict__ pv0, float* __restrict__ pv1)
{
    int id = blockIdx.x;
    if (id < 128) {
        bgemm_body<1>(ct_hi, ct_lo, qw_hi, qw_lo, nullptr, q_hi, q_lo,
                      2048, 2048, 2048, (id >> 4) * 128, (id & 15) * 128);
    } else {
        int id2 = id - 128;
        const int part = id2 / 96;
        const int t = id2 % 96;
        const int half = part & 1, isv = part >> 1;
        const int ko = half * 1024;
        const __nv_bfloat16* bh = (isv ? vw_hi : kw_hi) + ko;
        const __nv_bfloat16* bl = (isv ? vw_lo : kw_lo) + ko;
        float* P = isv ? (half ? pv1 : pv0) : (half ? pk1 : pk0);
        bgemm_body<0>(res_hi + ko, res_lo + ko, bh, bl, P, nullptr, nullptr,
                      512, 2048, 1024, (t >> 2) * 128, (t & 3) * 128);
    }
}

// gate + up, wave-smoothed: 888 CTAs = 3 x 296.
// ids [0,520): full-K tiles (gate 0..351, up 0..167).
// ids [520,888): split-K2 for up tiles 168..351 (tile-local partials).
__global__ __launch_bounds__(256, 2) void bgemm_gateup(
    const __nv_bfloat16* __restrict__ ct_hi, const __nv_bfloat16* __restrict__ ct_lo,
    const __nv_bfloat16* __restrict__ gw_hi, const __nv_bfloat16* __restrict__ gw_lo,
    const __nv_bfloat16* __restrict__ uw_hi, const __nv_bfloat16* __restrict__ uw_lo,
    float* __restrict__ gate, float* __restrict__ up,
    float* __restrict__ pg0, float* __restrict__ pg1)
{
    int id = blockIdx.x;
    if (id < 520) {
        int t = id;
        const __nv_bfloat16 *bh, *bl; float* C;
        if (t < 352) { bh = gw_hi; bl = gw_lo; C = gate; }
        else { t -= 352; bh = uw_hi; bl = uw_lo; C = up; }
        bgemm_body<0>(ct_hi, ct_lo, bh, bl, C, nullptr, nullptr,
                      5632, 2048, 2048, (t / 44) * 128, (t % 44) * 128);
    } else {
        int s = id - 520;                 // 0..367
        int half = s / 184, slot = s % 184;
        int u = 168 + slot;               // up tile index
        int m0 = (u / 44) * 128, n0 = (u % 44) * 128;
        int ko = half * 1024;
        float* P = (half ? pg1 : pg0) + (size_t)slot * 16384
                   - ((size_t)m0 * 128 + n0);
        bgemm_body<0>(ct_hi + ko, ct_lo + ko, uw_hi + ko, uw_lo + ko,
                      P, nullptr, nullptr, 128, 2048, 1024, m0, n0);
    }
}

// recombine split gateup tiles into up
__global__ void reduce_up(const float* __restrict__ pg0, const float* __restrict__ pg1,
                          float* __restrict__ up)
{
    int blk = blockIdx.x;                // 736 = 184 slots x 4
    int slot = blk >> 2, part = blk & 3;
    int u = 168 + slot;
    int m0 = (u / 44) * 128, n0 = (u % 44) * 128;
    const float4* a4 = (const float4*)(pg0 + (size_t)slot * 16384);
    const float4* b4 = (const float4*)(pg1 + (size_t)slot * 16384);
    int e = part * 1024 + threadIdx.x;
#pragma unroll
    for (int uu = 0; uu < 4; uu++, e += 256) {
        float4 a = a4[e], b = b4[e];
        float4 v = make_float4(a.x + b.x, a.y + b.y, a.z + b.z, a.w + b.w);
        int r = e >> 5;                  // 32 float4 per 128-col row
        int c = (e & 31) * 4;
        *(float4*)(up + (size_t)(m0 + r) * 5632 + n0 + c) = v;
    }
}

// ==================== fused: reduce + residual + rmsnorm + splits ==========
// x = P0 + P1 + (BIAS ? bias[row] : aux[row][:]);  optional res split of x;
// y = x * rsqrt(mean(x^2)+eps) * w; write y fp32 + hi/lo split.
template <int BIAS, int RES>
__global__ void fused_rms(const float* __restrict__ P0, const float* __restrict__ P1,
                          const float* __restrict__ aux, const float* __restrict__ w,
                          float* __restrict__ y,
                          __nv_bfloat16* __restrict__ yhi, __nv_bfloat16* __restrict__ ylo,
                          __nv_bfloat16* __restrict__ rhi, __nv_bfloat16* __restrict__ rlo)
{
    const int row = blockIdx.x;
    const int tid = threadIdx.x;
    const size_t b4 = (size_t)row * 512;
    float4 x[2];
    float ss = 0.f;
#pragma unroll
    for (int k = 0; k < 2; k++) {
        size_t i = b4 + tid + k * 256;
        float4 a = ((const float4*)P0)[i];
        float4 b = ((const float4*)P1)[i];
        float4 v = make_float4(a.x + b.x, a.y + b.y, a.z + b.z, a.w + b.w);
        if (BIAS) {
            float bb = aux[row];
            v.x += bb; v.y += bb; v.z += bb; v.w += bb;
        } else {
            float4 c = ((const float4*)aux)[i];
            v.x += c.x; v.y += c.y; v.z += c.z; v.w += c.w;
        }
        x[k] = v;
        ss += v.x * v.x + v.y * v.y + v.z * v.z + v.w * v.w;
    }
    __shared__ float red[256];
    red[tid] = ss;
    __syncthreads();
    for (int s = 128; s > 0; s >>= 1) {
        if (tid < s) red[tid] += red[tid + s];
        __syncthreads();
    }
    const float inv = rsqrtf(red[0] * (1.f / 2048.f) + 1e-6f);
#pragma unroll
    for (int k = 0; k < 2; k++) {
        size_t i = b4 + tid + k * 256;
        float4 v = x[k];
        if (RES) {
            uint32_t h0 = pack_bf2(v.x, v.y), h1 = pack_bf2(v.z, v.w);
            ((uint32_t*)rhi)[i * 2]     = h0;
            ((uint32_t*)rhi)[i * 2 + 1] = h1;
            __nv_bfloat162 a0 = *(__nv_bfloat162*)&h0;
            __nv_bfloat162 a1 = *(__nv_bfloat162*)&h1;
            ((uint32_t*)rlo)[i * 2] =
                pack_bf2(v.x - __bfloat162float(a0.x), v.y - __bfloat162float(a0.y));
            ((uint32_t*)rlo)[i * 2 + 1] =
                pack_bf2(v.z - __bfloat162float(a1.x), v.w - __bfloat162float(a1.y));
        }
        float4 wv = ((const float4*)w)[tid + k * 256];
        float4 yv = make_float4(v.x * inv * wv.x, v.y * inv * wv.y,
                                v.z * inv * wv.z, v.w * inv * wv.w);
        ((float4*)y)[i] = yv;
        uint32_t h0 = pack_bf2(yv.x, yv.y), h1 = pack_bf2(yv.z, yv.w);
        ((uint32_t*)yhi)[i * 2]     = h0;
        ((uint32_t*)yhi)[i * 2 + 1] = h1;
        __nv_bfloat162 a0 = *(__nv_bfloat162*)&h0;
        __nv_bfloat162 a1 = *(__nv_bfloat162*)&h1;
        ((uint32_t*)ylo)[i * 2] =
            pack_bf2(yv.x - __bfloat162float(a0.x), yv.y - __bfloat162float(a0.y));
        ((uint32_t*)ylo)[i * 2 + 1] =
            pack_bf2(yv.z - __bfloat162float(a1.x), yv.w - __bfloat162float(a1.y));
    }
}

// final reduce to output: out = P0 + P1 + ct
__global__ void reduce_out(const float* __restrict__ P0, const float* __restrict__ P1,
                           const float* __restrict__ aux, float* __restrict__ C, int n4)
{
    int i = blockIdx.x * 1024 + threadIdx.x;
#pragma unroll
    for (int u = 0; u < 4; u++, i += 256) {
        if (i < n4) {
            float4 a = ((const float4*)P0)[i];
            float4 b = ((const float4*)P1)[i];
            float4 c = ((const float4*)aux)[i];
            ((float4*)C)[i] = make_float4(a.x + b.x + c.x, a.y + b.y + c.y,
                                          a.z + b.z + c.z, a.w + b.w + c.w);
        }
    }
}

// fused K+V reduce
__global__ void reduce_kv(const float* __restrict__ pk0, const float* __restrict__ pk1,
                          const float* __restrict__ pv0, const float* __restrict__ pv1,
                          __nv_bfloat16* __restrict__ k_hi, __nv_bfloat16* __restrict__ k_lo,
                          __nv_bfloat16* __restrict__ v_hi, __nv_bfloat16* __restrict__ v_lo,
                          int n4each)
{
    int blk = blockIdx.x;
    const float *P0, *P1;
    __nv_bfloat16 *hi, *lo;
    int nblk = (n4each + 1023) / 1024;
    if (blk < nblk) { P0 = pk0; P1 = pk1; hi = k_hi; lo = k_lo; }
    else { blk -= nblk; P0 = pv0; P1 = pv1; hi = v_hi; lo = v_lo; }
    int i = blk * 1024 + threadIdx.x;
#pragma unroll
    for (int u = 0; u < 4; u++, i += 256) {
        if (i < n4each) {
            float4 a = ((const float4*)P0)[i];
            float4 b = ((const float4*)P1)[i];
            float4 v = make_float4(a.x + b.x, a.y + b.y, a.z + b.z, a.w + b.w);
            uint32_t h0 = pack_bf2(v.x, v.y), h1 = pack_bf2(v.z, v.w);
            ((uint32_t*)hi)[i * 2]     = h0;
            ((uint32_t*)hi)[i * 2 + 1] = h1;
            __nv_bfloat162 a0 = *(__nv_bfloat162*)&h0;
            __nv_bfloat162 a1 = *(__nv_bfloat162*)&h1;
            ((uint32_t*)lo)[i * 2] =
                pack_bf2(v.x - __bfloat162float(a0.x), v.y - __bfloat162float(a0.y));
            ((uint32_t*)lo)[i * 2 + 1] =
                pack_bf2(v.z - __bfloat162float(a1.x), v.w - __bfloat162float(a1.y));
        }
    }
}

// ==================== mega split ====================
struct SplitArgs {
    const float* src[9];
    __nv_bfloat16* hi[9];
    __nv_bfloat16* lo[9];
    int blk_start[10];
    int n4[9];
};

__global__ void megasplit_kernel(SplitArgs a)
{
    int blk = blockIdx.x;
    int j = 0;
#pragma unroll
    for (int t = 1; t < 9; t++)
        if (blk >= a.blk_start[t]) j = t;
    const float* src = a.src[j];
    __nv_bfloat16* hi = a.hi[j];
    __nv_bfloat16* lo = a.lo[j];
    const int n4 = a.n4[j];
    int i = (blk - a.blk_start[j]) * 1024 + threadIdx.x;
#pragma unroll
    for (int u = 0; u < 4; u++, i += 256) {
        if (i < n4) {
            float4 v = ((const float4*)src)[i];
            uint32_t h0 = pack_bf2(v.x, v.y), h1 = pack_bf2(v.z, v.w);
            ((uint32_t*)hi)[i * 2]     = h0;
            ((uint32_t*)hi)[i * 2 + 1] = h1;
            __nv_bfloat162 a0 = *(__nv_bfloat162*)&h0;
            __nv_bfloat162 a1 = *(__nv_bfloat162*)&h1;
            ((uint32_t*)lo)[i * 2] =
                pack_bf2(v.x - __bfloat162float(a0.x), v.y - __bfloat162float(a0.y));
            ((uint32_t*)lo)[i * 2 + 1] =
                pack_bf2(v.z - __bfloat162float(a1.x), v.w - __bfloat162float(a1.y));
        }
    }
}

// ==================== HMMA split-bf16 flash attention ======================
__global__ __launch_bounds__(128, 4) void attn_mma(
    const __nv_bfloat16* __restrict__ Qhi, const __nv_bfloat16* __restrict__ Qlo,
    const __nv_bfloat16* __restrict__ Khi, const __nv_bfloat16* __restrict__ Klo,
    const __nv_bfloat16* __restrict__ Vhi, const __nv_bfloat16* __restrict__ Vlo,
    __nv_bfloat16* __restrict__ Ohi, __nv_bfloat16* __restrict__ Olo)
{
    extern __shared__ char sm[];
    const int tid = threadIdx.x;
    const int wid = tid >> 5, lid = tid & 31;
    const int q0 = blockIdx.x * 64;
    const int head = blockIdx.y;
    const int kvoff = (head >> 2) * 64;
    const uint32_t sb = smem_u32(sm);
    const uint32_t sQh = sb, sQl = sb + 8192;
    const uint32_t sKV = sb + 16384;

#pragma unroll
    for (int i = 0; i < 4; i++) {
        int f = tid + i * 128;
        int r = f >> 3, c = f & 7;
        uint32_t off = (uint32_t)(r * 128) + (uint32_t)((c * 16) ^ ((r & 7) << 4));
        size_t g = (size_t)(q0 + r) * 2048 + head * 64 + c * 8;
        CP_ASYNC16(sQh + off, Qhi + g);
        CP_ASYNC16(sQl + off, Qlo + g);
    }
    CP_COMMIT();

#define ISSUE_KV(t0, st)                                                       \
    {                                                                          \
        uint32_t s_ = sKV + (uint32_t)(st) * 16384;                            \
        _Pragma("unroll")                                                      \
        for (int i_ = 0; i_ < 2; i_++) {                                       \
            int f_ = tid + i_ * 128;                                           \
            int r_ = f_ >> 3, c_ = f_ & 7;                                     \
            uint32_t o_ = (uint32_t)(r_ * 128) +                               \
                          (uint32_t)((c_ * 16) ^ ((r_ & 7) << 4));             \
            size_t g_ = (size_t)((t0) + r_) * 512 + kvoff + c_ * 8;            \
            CP_ASYNC16(s_ + o_,         Khi + g_);                             \
            CP_ASYNC16(s_ + 4096 + o_,  Klo + g_);                             \
            CP_ASYNC16(s_ + 8192 + o_,  Vhi + g_);                             \
            CP_ASYNC16(s_ + 12288 + o_, Vlo + g_);                             \
        }                                                                      \
    }

    ISSUE_KV(0, 0);  CP_COMMIT();
    ISSUE_KV(32, 1); CP_COMMIT();

    CP_WAIT1();
    __syncthreads();

    uint32_t qh[4][4], ql[4][4];
    {
        const int ar = (lid & 7) + ((lid >> 3) & 1) * 8;
        const int row = wid * 16 + ar;
        const uint32_t khalf = (uint32_t)((lid >> 4) & 1) * 16;
#pragma unroll
        for (int ks = 0; ks < 4; ks++) {
            uint32_t off = (uint32_t)(row * 128) +
                           ((khalf + (uint32_t)ks * 32) ^ ((uint32_t)(ar & 7) << 4));
            LDSM_X4(qh[ks][0], qh[ks][1], qh[ks][2], qh[ks][3], sQh + off);
            LDSM_X4(ql[ks][0], ql[ks][1], ql[ks][2], ql[ks][3], sQl + off);
        }
    }

    float acc_o[8][4];
#pragma unroll
    for (int d = 0; d < 8; d++)
#pragma unroll
        for (int e = 0; e < 4; e++) acc_o[d][e] = 0.f;
    float mr0 = -1e30f, mr1 = -1e30f, lr0 = 0.f, lr1 = 0.f;

    const int brS = (lid & 7) + ((lid >> 4) & 1) * 8;
    const uint32_t bkS = (uint32_t)((lid >> 3) & 1) * 16;
    const int trV = (lid & 7) + ((lid >> 3) & 1) * 8;
    const uint32_t dkV = (uint32_t)((lid >> 4) & 1) * 16;

    for (int t = 0; t < 96; t++) {
        const uint32_t st = sKV + (uint32_t)(t & 1) * 16384;

        float s[4][4];
#pragma unroll
        for (int nt = 0; nt < 4; nt++)
#pragma unroll
            for (int e = 0; e < 4; e++) s[nt][e] = 0.f;
#pragma unroll
        for (int ks = 0; ks < 4; ks++) {
            uint32_t bh[4][2], bl[4][2];
#pragma unroll
            for (int p = 0; p < 2; p++) {
                int rr = p * 16 + brS;
                uint32_t off = (uint32_t)(rr * 128) +
                               ((bkS + (uint32_t)ks * 32) ^ ((uint32_t)(rr & 7) << 4));
                LDSM_X4(bh[2*p][0], bh[2*p][1], bh[2*p+1][0], bh[2*p+1][1], st + off);
                LDSM_X4(bl[2*p][0], bl[2*p][1], bl[2*p+1][0], bl[2*p+1][1], st + 4096 + off);
            }
#pragma unroll
            for (int nt = 0; nt < 4; nt++) {
                MMA_BF16(s[nt], qh[ks], bh[nt]);
                MMA_BF16(s[nt], qh[ks], bl[nt]);
                MMA_BF16(s[nt], ql[ks], bh[nt]);
            }
        }

        float mn0 = mr0, mn1 = mr1;
#pragma unroll
        for (int nt = 0; nt < 4; nt++) {
            s[nt][0] *= 0.125f; s[nt][1] *= 0.125f;
            s[nt][2] *= 0.125f; s[nt][3] *= 0.125f;
            mn0 = fmaxf(mn0, fmaxf(s[nt][0], s[nt][1]));
            mn1 = fmaxf(mn1, fmaxf(s[nt][2], s[nt][3]));
        }
        mn0 = fmaxf(mn0, __shfl_xor_sync(0xffffffffu, mn0, 1));
        mn0 = fmaxf(mn0, __shfl_xor_sync(0xffffffffu, mn0, 2));
        mn1 = fmaxf(mn1, __shfl_xor_sync(0xffffffffu, mn1, 1));
        mn1 = fmaxf(mn1, __shfl_xor_sync(0xffffffffu, mn1, 2));
        float f0 = __expf(mr0 - mn0), f1 = __expf(mr1 - mn1);
        mr0 = mn0; mr1 = mn1;
        float ps0 = 0.f, ps1 = 0.f;
#pragma unroll
        for (int nt = 0; nt < 4; nt++) {
            s[nt][0] = __expf(s[nt][0] - mn0);
            s[nt][1] = __expf(s[nt][1] - mn0);
            s[nt][2] = __expf(s[nt][2] - mn1);
            s[nt][3] = __expf(s[nt][3] - mn1);
            ps0 += s[nt][0] + s[nt][1];
            ps1 += s[nt][2] + s[nt][3];
        }
        lr0 = lr0 * f0 + ps0;
        lr1 = lr1 * f1 + ps1;
#pragma unroll
        for (int d = 0; d < 8; d++) {
            acc_o[d][0] *= f0; acc_o[d][1] *= f0;
            acc_o[d][2] *= f1; acc_o[d][3] *= f1;
        }

#pragma unroll
        for (int j = 0; j < 2; j++) {
            uint32_t ah[4], al[4];
            {
                float p00 = s[2*j][0],   p01 = s[2*j][1];
                float p02 = s[2*j][2],   p03 = s[2*j][3];
                float p10 = s[2*j+1][0], p11 = s[2*j+1][1];
                float p12 = s[2*j+1][2], p13 = s[2*j+1][3];
                ah[0] = pack_bf2(p00, p01); ah[1] = pack_bf2(p02, p03);
                ah[2] = pack_bf2(p10, p11); ah[3] = pack_bf2(p12, p13);
#pragma unroll
                for (int e = 0; e < 4; e++) {
                    __nv_bfloat162 hh = *(__nv_bfloat162*)&ah[e];
                    float x0, x1;
                    if (e == 0) { x0 = p00; x1 = p01; }
                    else if (e == 1) { x0 = p02; x1 = p03; }
                    else if (e == 2) { x0 = p10; x1 = p11; }
                    else { x0 = p12; x1 = p13; }
                    al[e] = pack_bf2(x0 - __bfloat162float(hh.x),
                                     x1 - __bfloat162float(hh.y));
                }
            }
            const int rr = j * 16 + trV;
#pragma unroll
            for (int dp = 0; dp < 4; dp++) {
                uint32_t off = (uint32_t)(rr * 128) +
                               ((dkV + (uint32_t)dp * 32) ^ ((uint32_t)(rr & 7) << 4));
                uint32_t vh[4], vl[4];
                LDSM_X4_T(vh[0], vh[1], vh[2], vh[3], st + 8192 + off);
                LDSM_X4_T(vl[0], vl[1], vl[2], vl[3], st + 12288 + off);
                uint32_t b0h[2] = {vh[0], vh[1]}, b1h[2] = {vh[2], vh[3]};
                uint32_t b0l[2] = {vl[0], vl[1]}, b1l[2] = {vl[2], vl[3]};
                MMA_BF16(acc_o[2*dp],   ah, b0h);
                MMA_BF16(acc_o[2*dp],   ah, b0l);
                MMA_BF16(acc_o[2*dp],   al, b0h);
                MMA_BF16(acc_o[2*dp+1], ah, b1h);
                MMA_BF16(acc_o[2*dp+1], ah, b1l);
                MMA_BF16(acc_o[2*dp+1], al, b1h);
            }
        }

        __syncthreads();
        if (t + 2 < 96) ISSUE_KV((t + 2) * 32, t & 1);
        CP_COMMIT();
        if (t + 1 < 96) { CP_WAIT1(); __syncthreads(); }
    }

    lr0 += __shfl_xor_sync(0xffffffffu, lr0, 1);
    lr0 += __shfl_xor_sync(0xffffffffu, lr0, 2);
    lr1 += __shfl_xor_sync(0xffffffffu, lr1, 1);
    lr1 += __shfl_xor_sync(0xffffffffu, lr1, 2);
    float il0 = 1.f / lr0, il1 = 1.f / lr1;
    const int row0 = q0 + wid * 16 + (lid >> 2);
    const int col0 = head * 64 + (lid & 3) * 2;
#pragma unroll
    for (int d = 0; d < 8; d++) {
        int col = col0 + d * 8;
        float o0 = acc_o[d][0] * il0, o1 = acc_o[d][1] * il0;
        float o2 = acc_o[d][2] * il1, o3 = acc_o[d][3] * il1;
        uint32_t h0 = pack_bf2(o0, o1), h1 = pack_bf2(o2, o3);
        *(uint32_t*)(Ohi + (size_t)row0 * 2048 + col) = h0;
        *(uint32_t*)(Ohi + (size_t)(row0 + 8) * 2048 + col) = h1;
        __nv_bfloat162 hh0 = *(__nv_bfloat162*)&h0;
        __nv_bfloat162 hh1 = *(__nv_bfloat162*)&h1;
        *(uint32_t*)(Olo + (size_t)row0 * 2048 + col) =
            pack_bf2(o0 - __bfloat162float(hh0.x), o1 - __bfloat162float(hh0.y));
        *(uint32_t*)(Olo + (size_t)(row0 + 8) * 2048 + col) =
            pack_bf2(o2 - __bfloat162float(hh1.x), o3 - __bfloat162float(hh1.y));
    }
}

// -------------------- misc elementwise --------------------
__global__ void transpose_split(const float* __restrict__ x,
                                __nv_bfloat16* __restrict__ hiT,
                                __nv_bfloat16* __restrict__ loT, int R, int C)
{
    __shared__ float t[32][33];
    int c0 = blockIdx.x * 32, r0 = blockIdx.y * 32;
    for (int i = threadIdx.y; i < 32; i += 8)
        t[i][threadIdx.x] = x[(size_t)(r0 + i) * C + c0 + threadIdx.x];
    __syncthreads();
    for (int i = threadIdx.y; i < 32; i += 8) {
        float v = t[threadIdx.x][i];
        __nv_bfloat16 h = __float2bfloat16(v);
        size_t o = (size_t)(c0 + i) * R + r0 + threadIdx.x;
        hiT[o] = h;
        loT[o] = __float2bfloat16(v - __bfloat162float(h));
    }
}

__global__ void swiglu_split(const float* __restrict__ g, const float* __restrict__ u,
                             __nv_bfloat16* __restrict__ hi, __nv_bfloat16* __restrict__ lo,
                             int n)
{
    int i = blockIdx.x * blockDim.x + threadIdx.x;
    if (i < n) {
        float x = g[i];
        float v = (x / (1.f + __expf(-x))) * u[i];
        __nv_bfloat16 h = __float2bfloat16(v);
        hi[i] = h;
        lo[i] = __float2bfloat16(v - __bfloat162float(h));
    }
}

// -------------------- orchestration --------------------
static const int SMEM_GEMM = 3 * 32768;
static const int SMEM_ATTN = 16384 + 2 * 16384;

extern "C" void kernel_launch(void* const* d_in, const int* in_sizes, int n_in,
                              void* d_out, int out_size)
{
    (void)in_sizes; (void)n_in; (void)out_size;
    const float* hidden      = (const float*)d_in[0];
    const float* comp_w      = (const float*)d_in[1];
    const float* comp_b      = (const float*)d_in[2];
    const float* q_w         = (const float*)d_in[3];
    const float* k_w         = (const float*)d_in[4];
    const float* v_w         = (const float*)d_in[5];
    const float* o_w         = (const float*)d_in[6];
    const float* attn_norm_w = (const float*)d_in[7];
    const float* mlp_norm_w  = (const float*)d_in[8];
    const float* gate_w      = (const float*)d_in[9];
    const float* up_w        = (const float*)d_in[10];
    const float* down_w      = (const float*)d_in[11];
    float* out = (float*)d_out;

    cudaFuncSetAttribute(bgemm_splitk, cudaFuncAttributeMaxDynamicSharedMemorySize, SMEM_GEMM);
    cudaFuncSetAttribute(bgemm_qkv,    cudaFuncAttributeMaxDynamicSharedMemorySize, SMEM_GEMM);
    cudaFuncSetAttribute(bgemm_gateup, cudaFuncAttributeMaxDynamicSharedMemorySize, SMEM_GEMM);
    cudaFuncSetAttribute(attn_mma,     cudaFuncAttributeMaxDynamicSharedMemorySize, SMEM_ATTN);

    float *ct, *gate, *up, *p0, *p1, *pk0, *pk1, *pv0, *pv1, *pg0, *pg1;
    cudaGetSymbolAddress((void**)&ct,   g_ct);
    cudaGetSymbolAddress((void**)&gate, g_gate);
    cudaGetSymbolAddress((void**)&up,   g_up);
    cudaGetSymbolAddress((void**)&p0,   g_p0);
    cudaGetSymbolAddress((void**)&p1,   g_p1);
    cudaGetSymbolAddress((void**)&pk0,  g_pk0);
    cudaGetSymbolAddress((void**)&pk1,  g_pk1);
    cudaGetSymbolAddress((void**)&pv0,  g_pv0);
    cudaGetSymbolAddress((void**)&pv1,  g_pv1);
    cudaGetSymbolAddress((void**)&pg0,  g_pg0);
    cudaGetSymbolAddress((void**)&pg1,  g_pg1);

    __nv_bfloat16 *res_hi, *res_lo, *ct_hi, *ct_lo, *ao_hi, *ao_lo, *ga_hi, *ga_lo,
                  *hT_hi, *hT_lo, *q_hi, *q_lo, *k_hi, *k_lo, *v_hi, *v_lo,
                  *cw_hi, *cw_lo, *qw_hi, *qw_lo, *kw_hi, *kw_lo,
                  *vw_hi, *vw_lo, *ow_hi, *ow_lo, *gw_hi, *gw_lo, *uw_hi, *uw_lo,
                  *dw_hi, *dw_lo;
    cudaGetSymbolAddress((void**)&res_hi, g_res_hi); cudaGetSymbolAddress((void**)&res_lo, g_res_lo);
    cudaGetSymbolAddress((void**)&ct_hi,  g_ct_hi);  cudaGetSymbolAddress((void**)&ct_lo,  g_ct_lo);
    cudaGetSymbolAddress((void**)&ao_hi,  g_ao_hi);  cudaGetSymbolAddress((void**)&ao_lo,  g_ao_lo);
    cudaGetSymbolAddress((void**)&ga_hi,  g_ga_hi);  cudaGetSymbolAddress((void**)&ga_lo,  g_ga_lo);
    cudaGetSymbolAddress((void**)&hT_hi,  g_hT_hi);  cudaGetSymbolAddress((void**)&hT_lo,  g_hT_lo);
    cudaGetSymbolAddress((void**)&q_hi,   g_q_hi);   cudaGetSymbolAddress((void**)&q_lo,   g_q_lo);
    cudaGetSymbolAddress((void**)&k_hi,   g_k_hi);   cudaGetSymbolAddress((void**)&k_lo,   g_k_lo);
    cudaGetSymbolAddress((void**)&v_hi,   g_v_hi);   cudaGetSymbolAddress((void**)&v_lo,   g_v_lo);
    cudaGetSymbolAddress((void**)&cw_hi,  g_cw_hi);  cudaGetSymbolAddress((void**)&cw_lo,  g_cw_lo);
    cudaGetSymbolAddress((void**)&qw_hi,  g_qw_hi);  cudaGetSymbolAddress((void**)&qw_lo,  g_qw_lo);
    cudaGetSymbolAddress((void**)&kw_hi,  g_kw_hi);  cudaGetSymbolAddress((void**)&kw_lo,  g_kw_lo);
    cudaGetSymbolAddress((void**)&vw_hi,  g_vw_hi);  cudaGetSymbolAddress((void**)&vw_lo,  g_vw_lo);
    cudaGetSymbolAddress((void**)&ow_hi,  g_ow_hi);  cudaGetSymbolAddress((void**)&ow_lo,  g_ow_lo);
    cudaGetSymbolAddress((void**)&gw_hi,  g_gw_hi);  cudaGetSymbolAddress((void**)&gw_lo,  g_gw_lo);
    cudaGetSymbolAddress((void**)&uw_hi,  g_uw_hi);  cudaGetSymbolAddress((void**)&uw_lo,  g_uw_lo);
    cudaGetSymbolAddress((void**)&dw_hi,  g_dw_hi);  cudaGetSymbolAddress((void**)&dw_lo,  g_dw_lo);

    // ---- one mega-split launch for all conversions ----
    {
        SplitArgs a;
        const float* srcs[9] = {comp_w, q_w, k_w, v_w, o_w, gate_w, up_w, down_w, hidden};
        __nv_bfloat16* his[9] = {cw_hi, qw_hi, kw_hi, vw_hi, ow_hi, gw_hi, uw_hi, dw_hi, res_hi};
        __nv_bfloat16* los[9] = {cw_lo, qw_lo, kw_lo, vw_lo, ow_lo, gw_lo, uw_lo, dw_lo, res_lo};
        int ns[9] = {1024*2048, 2048*2048, 512*2048, 512*2048, 2048*2048,
                     5632*2048, 5632*2048, 2048*5632, 2048*2048};
        int blk = 0;
        for (int j = 0; j < 9; j++) {
            a.src[j] = srcs[j]; a.hi[j] = his[j]; a.lo[j] = los[j];
            a.n4[j] = ns[j] / 4;
            a.blk_start[j] = blk;
            blk += (a.n4[j] + 1023) / 1024;
        }
        a.blk_start[9] = blk;
        megasplit_kernel<<<blk, 256>>>(a);
    }
    transpose_split<<<dim3(64, 64), dim3(32, 8)>>>(hidden, hT_hi, hT_lo, 2048, 2048);

    const int N4 = 1024 * 2048 / 4;
    const int KV4 = 3072 * 512 / 4;

    // compressed-chain via fused kernels (no fp32 'compressed' array)
    bgemm_splitk<<<256, 256, SMEM_GEMM>>>(cw_hi, cw_lo, hT_hi, hT_lo,
                                          p0, p1, 2048, 2048, 1024);
    fused_rms<1,1><<<1024, 256>>>(p0, p1, comp_b, attn_norm_w,
        ct, ct_hi, ct_lo, res_hi + 2048 * 2048, res_lo + 2048 * 2048);

    for (int layer = 0; layer < 2; layer++) {
        bgemm_qkv<<<512, 256, SMEM_GEMM>>>(ct_hi, ct_lo, res_hi, res_lo,
            qw_hi, qw_lo, kw_hi, kw_lo, vw_hi, vw_lo,
            q_hi, q_lo, pk0, pk1, pv0, pv1);
        reduce_kv<<<2 * (KV4 / 1024), 256>>>(pk0, pk1, pv0, pv1,
                                             k_hi, k_lo, v_hi, v_lo, KV4);

        attn_mma<<<dim3(16, 32), 128, SMEM_ATTN>>>(q_hi, q_lo, k_hi, k_lo,
                                                   v_hi, v_lo, ao_hi, ao_lo);

        // o-proj + residual(ct) + mlp-rmsnorm -> ct (=ct2)
        bgemm_splitk<<<256, 256, SMEM_GEMM>>>(ao_hi, ao_lo, ow_hi, ow_lo,
                                              p0, p1, 2048, 2048, 1024);
        fused_rms<0,0><<<1024, 256>>>(p0, p1, ct, mlp_norm_w,
                                      ct, ct_hi, ct_lo, nullptr, nullptr);

        // gate/up: 888 CTAs = 3 exact waves (520 full + 368 split halves)
        bgemm_gateup<<<888, 256, SMEM_GEMM>>>(ct_hi, ct_lo, gw_hi, gw_lo,
                                              uw_hi, uw_lo, gate, up, pg0, pg1);
        reduce_up<<<736, 256>>>(pg0, pg1, up);
        swiglu_split<<<(1024 * 5632 + 255) / 256, 256>>>(gate, up, ga_hi, ga_lo,
                                                         1024 * 5632);

        // down-proj
        bgemm_splitk<<<256, 256, SMEM_GEMM>>>(ga_hi, ga_lo, dw_hi, dw_lo,
                                              p0, p1, 2048, 5632, 2816);
        if (layer == 0) {
            // + ct2, emit residual split, attn-rmsnorm -> ct for layer 1
            fused_rms<0,1><<<1024, 256>>>(p0, p1, ct, attn_norm_w,
                ct, ct_hi, ct_lo, res_hi + 2048 * 2048, res_lo + 2048 * 2048);
        } else {
            reduce_out<<<N4 / 1024, 256>>>(p0, p1, ct, out, N4);
        }
    }
}

// round 16
// speedup vs baseline: 1.1390x; 1.0576x over previous
#include <cuda_runtime.h>
#include <cuda_bf16.h>
#include <cstdint>
#include <math.h>

// ===========================================================================
// S=2048, H=2048, COMP=1024, T=3072, KV_DIM=512, FF=5632, NH=32, NKV=8,
// HD=64, DEPTH=2. mma.sync.m16n8k16 bf16 hi/lo 3-product split everywhere.
// R14: fix swiglu_plain coverage bug (missing 4x per-thread loop) from R12;
//      retains mainloop cp.async reorder + swiglu-in-reduce fusion.
// ===========================================================================

// -------------------- device-global scratch (no allocs) --------------------
__device__ float g_ct[1024 * 2048];
__device__ float g_gate[1024 * 5632];
__device__ float g_up[1024 * 5632];
__device__ float g_p0[1024 * 2048], g_p1[1024 * 2048];
__device__ float g_pk0[3072 * 512], g_pk1[3072 * 512];
__device__ float g_pv0[3072 * 512], g_pv1[3072 * 512];
__device__ float g_pg0[184 * 16384], g_pg1[184 * 16384];

__device__ __nv_bfloat16 g_res_hi[3072 * 2048], g_res_lo[3072 * 2048];
__device__ __nv_bfloat16 g_ct_hi[1024 * 2048], g_ct_lo[1024 * 2048];
__device__ __nv_bfloat16 g_ao_hi[1024 * 2048], g_ao_lo[1024 * 2048];
__device__ __nv_bfloat16 g_ga_hi[1024 * 5632], g_ga_lo[1024 * 5632];
__device__ __nv_bfloat16 g_hT_hi[2048 * 2048], g_hT_lo[2048 * 2048];

__device__ __nv_bfloat16 g_q_hi[1024 * 2048], g_q_lo[1024 * 2048];
__device__ __nv_bfloat16 g_k_hi[3072 * 512],  g_k_lo[3072 * 512];
__device__ __nv_bfloat16 g_v_hi[3072 * 512],  g_v_lo[3072 * 512];

__device__ __nv_bfloat16 g_cw_hi[1024 * 2048], g_cw_lo[1024 * 2048];
__device__ __nv_bfloat16 g_qw_hi[2048 * 2048], g_qw_lo[2048 * 2048];
__device__ __nv_bfloat16 g_kw_hi[512 * 2048],  g_kw_lo[512 * 2048];
__device__ __nv_bfloat16 g_vw_hi[512 * 2048],  g_vw_lo[512 * 2048];
__device__ __nv_bfloat16 g_ow_hi[2048 * 2048], g_ow_lo[2048 * 2048];
__device__ __nv_bfloat16 g_gw_hi[5632 * 2048], g_gw_lo[5632 * 2048];
__device__ __nv_bfloat16 g_uw_hi[5632 * 2048], g_uw_lo[5632 * 2048];
__device__ __nv_bfloat16 g_dw_hi[2048 * 5632], g_dw_lo[2048 * 5632];

// -------------------- helpers --------------------
__device__ __forceinline__ uint32_t smem_u32(const void* p) {
    return (uint32_t)__cvta_generic_to_shared(p);
}

#define LDSM_X4(r0, r1, r2, r3, addr)                                          \
    asm volatile("ldmatrix.sync.aligned.m8n8.x4.shared.b16 {%0,%1,%2,%3}, [%4];" \
                 : "=r"(r0), "=r"(r1), "=r"(r2), "=r"(r3) : "r"(addr))
#define LDSM_X4_T(r0, r1, r2, r3, addr)                                        \
    asm volatile("ldmatrix.sync.aligned.m8n8.x4.trans.shared.b16 {%0,%1,%2,%3}, [%4];" \
                 : "=r"(r0), "=r"(r1), "=r"(r2), "=r"(r3) : "r"(addr))

#define MMA_BF16(ac, ar, br)                                                   \
    asm volatile(                                                              \
        "mma.sync.aligned.m16n8k16.row.col.f32.bf16.bf16.f32 "                 \
        "{%0,%1,%2,%3},{%4,%5,%6,%7},{%8,%9},{%0,%1,%2,%3};"                   \
        : "+f"((ac)[0]), "+f"((ac)[1]), "+f"((ac)[2]), "+f"((ac)[3])           \
        : "r"((ar)[0]), "r"((ar)[1]), "r"((ar)[2]), "r"((ar)[3]),              \
          "r"((br)[0]), "r"((br)[1]))

#define CP_ASYNC16(dst, src)                                                   \
    asm volatile("cp.async.cg.shared.global [%0], [%1], 16;" :: "r"(dst), "l"(src))
#define CP_COMMIT() asm volatile("cp.async.commit_group;")
#define CP_WAIT1()  asm volatile("cp.async.wait_group 1;")

__device__ __forceinline__ uint32_t pack_bf2(float x, float y) {
    __nv_bfloat162 h = __floats2bfloat162_rn(x, y);
    return *(uint32_t*)&h;
}

// ==================== HMMA split-bf16 GEMM body (8 warps, 32x64) ===========
__device__ __forceinline__ void load_stage(
    uint32_t sb, int kc, int tid, int m0, int n0, int K,
    const __nv_bfloat16* __restrict__ Ahi, const __nv_bfloat16* __restrict__ Alo,
    const __nv_bfloat16* __restrict__ Bhi, const __nv_bfloat16* __restrict__ Blo)
{
    const int kb = kc * 32;
#pragma unroll
    for (int i = 0; i < 2; i++) {
        int f = tid + i * 256;
        int r = f >> 2, c = f & 3;
        uint32_t off = (uint32_t)(r * 64) +
                       (uint32_t)((c * 16) ^ (((r >> 1) & 3) << 4));
        size_t ga = (size_t)(m0 + r) * K + kb + c * 8;
        size_t gb = (size_t)(n0 + r) * K + kb + c * 8;
        CP_ASYNC16(sb + off,         Ahi + ga);
        CP_ASYNC16(sb + 8192 + off,  Alo + ga);
        CP_ASYNC16(sb + 16384 + off, Bhi + gb);
        CP_ASYNC16(sb + 24576 + off, Blo + gb);
    }
}

template <int OUT>
__device__ __forceinline__ void bgemm_body(
    const __nv_bfloat16* __restrict__ Ahi, const __nv_bfloat16* __restrict__ Alo,
    const __nv_bfloat16* __restrict__ Bhi, const __nv_bfloat16* __restrict__ Blo,
    float* __restrict__ C,
    __nv_bfloat16* __restrict__ Chi, __nv_bfloat16* __restrict__ Clo,
    int N, int K, int Klen, int m0, int n0)
{
    extern __shared__ char dsm[];
    const int tid = threadIdx.x;
    const int wid = tid >> 5, lid = tid & 31;
    const int wm = wid & 3, wn = wid >> 2;
    const uint32_t sbase = smem_u32(dsm);

    const int arow = wm * 32 + (lid & 7) + ((lid >> 3) & 1) * 8;
    const uint32_t a_base = (uint32_t)(arow * 64);
    const uint32_t a_sw = (uint32_t)(((arow >> 1) & 3) << 4);
    const uint32_t a_k = (uint32_t)((lid >> 4) & 1) * 16;

    const int brow = wn * 64 + (lid & 7) + ((lid >> 4) & 1) * 8;
    const uint32_t b_base = (uint32_t)(brow * 64);
    const uint32_t b_sw = (uint32_t)(((brow >> 1) & 3) << 4);
    const uint32_t b_k = (uint32_t)((lid >> 3) & 1) * 16;

    float acc[2][8][4];
#pragma unroll
    for (int mt = 0; mt < 2; mt++)
#pragma unroll
        for (int nt = 0; nt < 8; nt++)
#pragma unroll
            for (int e = 0; e < 4; e++) acc[mt][nt][e] = 0.f;

    const int NK = Klen / 32;
    load_stage(sbase, 0, tid, m0, n0, K, Ahi, Alo, Bhi, Blo);
    CP_COMMIT();
    load_stage(sbase + 32768, 1, tid, m0, n0, K, Ahi, Alo, Bhi, Blo);
    CP_COMMIT();

    auto ks_block = [&](uint32_t st, int ks) {
        const uint32_t ako = (a_k + (uint32_t)ks * 32) ^ a_sw;
        const uint32_t bko = (b_k + (uint32_t)ks * 32) ^ b_sw;
        uint32_t ah[2][4], al[2][4], bb[8][2];
#pragma unroll
        for (int mt = 0; mt < 2; mt++) {
            LDSM_X4(ah[mt][0], ah[mt][1], ah[mt][2], ah[mt][3],
                    st + a_base + (uint32_t)mt * 1024 + ako);
            LDSM_X4(al[mt][0], al[mt][1], al[mt][2], al[mt][3],
                    st + 8192 + a_base + (uint32_t)mt * 1024 + ako);
        }
#pragma unroll
        for (int p = 0; p < 4; p++) {
            LDSM_X4(bb[2*p][0], bb[2*p][1], bb[2*p+1][0], bb[2*p+1][1],
                    st + 16384 + b_base + (uint32_t)p * 1024 + bko);
        }
#pragma unroll
        for (int nt = 0; nt < 8; nt++)
#pragma unroll
            for (int mt = 0; mt < 2; mt++)
                MMA_BF16(acc[mt][nt], ah[mt], bb[nt]);
#pragma unroll
        for (int nt = 0; nt < 8; nt++)
#pragma unroll
            for (int mt = 0; mt < 2; mt++)
                MMA_BF16(acc[mt][nt], al[mt], bb[nt]);
#pragma unroll
        for (int p = 0; p < 4; p++) {
            LDSM_X4(bb[2*p][0], bb[2*p][1], bb[2*p+1][0], bb[2*p+1][1],
                    st + 24576 + b_base + (uint32_t)p * 1024 + bko);
        }
#pragma unroll
        for (int nt = 0; nt < 8; nt++)
#pragma unroll
            for (int mt = 0; mt < 2; mt++)
                MMA_BF16(acc[mt][nt], ah[mt], bb[nt]);
    };

    for (int kc = 0; kc < NK; kc++) {
        CP_WAIT1();
        __syncthreads();
        const uint32_t st = sbase + (uint32_t)(kc % 3) * 32768;
        ks_block(st, 0);
        if (kc + 2 < NK)
            load_stage(sbase + (uint32_t)((kc + 2) % 3) * 32768, kc + 2, tid,
                       m0, n0, K, Ahi, Alo, Bhi, Blo);
        CP_COMMIT();
        ks_block(st, 1);
    }

    const int grow0 = m0 + wm * 32 + (lid >> 2);
    const int gcol0 = n0 + wn * 64 + (lid & 3) * 2;
#pragma unroll
    for (int mt = 0; mt < 2; mt++) {
#pragma unroll
        for (int nt = 0; nt < 8; nt++) {
            int r0 = grow0 + mt * 16;
            int c0 = gcol0 + nt * 8;
            float2 v0 = make_float2(acc[mt][nt][0], acc[mt][nt][1]);
            float2 v1 = make_float2(acc[mt][nt][2], acc[mt][nt][3]);
            if (OUT == 0) {
                *(float2*)(C + (size_t)r0 * N + c0) = v0;
                *(float2*)(C + (size_t)(r0 + 8) * N + c0) = v1;
            } else {
                uint32_t h0 = pack_bf2(v0.x, v0.y);
                uint32_t h1 = pack_bf2(v1.x, v1.y);
                *(uint32_t*)(Chi + (size_t)r0 * N + c0) = h0;
                *(uint32_t*)(Chi + (size_t)(r0 + 8) * N + c0) = h1;
                __nv_bfloat162 hh0 = *(__nv_bfloat162*)&h0;
                __nv_bfloat162 hh1 = *(__nv_bfloat162*)&h1;
                *(uint32_t*)(Clo + (size_t)r0 * N + c0) =
                    pack_bf2(v0.x - __bfloat162float(hh0.x),
                             v0.y - __bfloat162float(hh0.y));
                *(uint32_t*)(Clo + (size_t)(r0 + 8) * N + c0) =
                    pack_bf2(v1.x - __bfloat162float(hh1.x),
                             v1.y - __bfloat162float(hh1.y));
            }
        }
    }
}

__global__ __launch_bounds__(256, 2) void bgemm_splitk(
    const __nv_bfloat16* __restrict__ Ahi, const __nv_bfloat16* __restrict__ Alo,
    const __nv_bfloat16* __restrict__ Bhi, const __nv_bfloat16* __restrict__ Blo,
    float* __restrict__ P0, float* __restrict__ P1,
    int N, int K, int Khalf)
{
    const int per = gridDim.x >> 1;
    int id = blockIdx.x;
    const int half = (id >= per) ? 1 : 0;
    if (half) id -= per;
    const int ntn = N >> 7;
    const int m0 = (id / ntn) * 128, n0 = (id % ntn) * 128;
    const int ko = half * Khalf;
    bgemm_body<0>(Ahi + ko, Alo + ko, Bhi + ko, Blo + ko,
                  half ? P1 : P0, nullptr, nullptr, N, K, Khalf, m0, n0);
}

__global__ __launch_bounds__(256, 2) void bgemm_qkv(
    const __nv_bfloat16* __restrict__ ct_hi, const __nv_bfloat16* __restrict__ ct_lo,
    const __nv_bfloat16* __restrict__ res_hi, const __nv_bfloat16* __restrict__ res_lo,
    const __nv_bfloat16* __restrict__ qw_hi, const __nv_bfloat16* __restrict__ qw_lo,
    const __nv_bfloat16* __restrict__ kw_hi, const __nv_bfloat16* __restrict__ kw_lo,
    const __nv_bfloat16* __restrict__ vw_hi, const __nv_bfloat16* __restrict__ vw_lo,
    __nv_bfloat16* __restrict__ q_hi, __nv_bfloat16* __restrict__ q_lo,
    float* __restrict__ pk0, float* __restrict__ pk1,
    float* __restrict__ pv0, float* __restrict__ pv1)
{
    int id = blockIdx.x;
    if (id < 128) {
        bgemm_body<1>(ct_hi, ct_lo, qw_hi, qw_lo, nullptr, q_hi, q_lo,
                      2048, 2048, 2048, (id >> 4) * 128, (id & 15) * 128);
    } else {
        int id2 = id - 128;
        const int part = id2 / 96;
        const int t = id2 % 96;
        const int half = part & 1, isv = part >> 1;
        const int ko = half * 1024;
        const __nv_bfloat16* bh = (isv ? vw_hi : kw_hi) + ko;
        const __nv_bfloat16* bl = (isv ? vw_lo : kw_lo) + ko;
        float* P = isv ? (half ? pv1 : pv0) : (half ? pk1 : pk0);
        bgemm_body<0>(res_hi + ko, res_lo + ko, bh, bl, P, nullptr, nullptr,
                      512, 2048, 1024, (t >> 2) * 128, (t & 3) * 128);
    }
}

// gate + up, wave-smoothed: 888 CTAs.
__global__ __launch_bounds__(256, 2) void bgemm_gateup(
    const __nv_bfloat16* __restrict__ ct_hi, const __nv_bfloat16* __restrict__ ct_lo,
    const __nv_bfloat16* __restrict__ gw_hi, const __nv_bfloat16* __restrict__ gw_lo,
    const __nv_bfloat16* __restrict__ uw_hi, const __nv_bfloat16* __restrict__ uw_lo,
    float* __restrict__ gate, float* __restrict__ up,
    float* __restrict__ pg0, float* __restrict__ pg1)
{
    int id = blockIdx.x;
    if (id < 520) {
        int t = id;
        const __nv_bfloat16 *bh, *bl; float* C;
        if (t < 352) { bh = gw_hi; bl = gw_lo; C = gate; }
        else { t -= 352; bh = uw_hi; bl = uw_lo; C = up; }
        bgemm_body<0>(ct_hi, ct_lo, bh, bl, C, nullptr, nullptr,
                      5632, 2048, 2048, (t / 44) * 128, (t % 44) * 128);
    } else {
        int s = id - 520;
        int half = s / 184, slot = s % 184;
        int u = 168 + slot;
        int m0 = (u / 44) * 128, n0 = (u % 44) * 128;
        int ko = half * 1024;
        float* P = (half ? pg1 : pg0) + (size_t)slot * 16384
                   - ((size_t)m0 * 128 + n0);
        bgemm_body<0>(ct_hi + ko, ct_lo + ko, uw_hi + ko, uw_lo + ko,
                      P, nullptr, nullptr, 128, 2048, 1024, m0, n0);
    }
}

// recombine split up tiles + fused swiglu -> ga hi/lo
__global__ void reduce_up_swiglu(
    const float* __restrict__ pg0, const float* __restrict__ pg1,
    const float* __restrict__ gate,
    __nv_bfloat16* __restrict__ ga_hi, __nv_bfloat16* __restrict__ ga_lo)
{
    int blk = blockIdx.x;                // 736 = 184 slots x 4
    int slot = blk >> 2, part = blk & 3;
    int u = 168 + slot;
    int m0 = (u / 44) * 128, n0 = (u % 44) * 128;
    const float4* a4 = (const float4*)(pg0 + (size_t)slot * 16384);
    const float4* b4 = (const float4*)(pg1 + (size_t)slot * 16384);
    int e = part * 1024 + threadIdx.x;
#pragma unroll
    for (int uu = 0; uu < 4; uu++, e += 256) {
        float4 a = a4[e], b = b4[e];
        float4 uv = make_float4(a.x + b.x, a.y + b.y, a.z + b.z, a.w + b.w);
        int r = e >> 5;
        int c = (e & 31) * 4;
        size_t off = (size_t)(m0 + r) * 5632 + n0 + c;
        float4 gv = *(const float4*)(gate + off);
        float4 v;
        v.x = (gv.x / (1.f + __expf(-gv.x))) * uv.x;
        v.y = (gv.y / (1.f + __expf(-gv.y))) * uv.y;
        v.z = (gv.z / (1.f + __expf(-gv.z))) * uv.z;
        v.w = (gv.w / (1.f + __expf(-gv.w))) * uv.w;
        uint32_t h0 = pack_bf2(v.x, v.y), h1 = pack_bf2(v.z, v.w);
        *(uint32_t*)(ga_hi + off)     = h0;
        *(uint32_t*)(ga_hi + off + 2) = h1;
        __nv_bfloat162 a0 = *(__nv_bfloat162*)&h0;
        __nv_bfloat162 a1 = *(__nv_bfloat162*)&h1;
        *(uint32_t*)(ga_lo + off) =
            pack_bf2(v.x - __bfloat162float(a0.x), v.y - __bfloat162float(a0.y));
        *(uint32_t*)(ga_lo + off + 2) =
            pack_bf2(v.z - __bfloat162float(a1.x), v.w - __bfloat162float(a1.y));
    }
}

// swiglu over the NON-split region: rows [0,384) all cols + rows [384,512) cols [0,4608)
// 672 blocks x 256 threads x 4 f4/thread = 688128 f4 (FIXED: restored 4x loop)
__global__ void swiglu_plain(const float* __restrict__ g, const float* __restrict__ u,
                             __nv_bfloat16* __restrict__ hi, __nv_bfloat16* __restrict__ lo)
{
    const int REG_A4 = 540672;            // 384*5632/4
    int f4 = blockIdx.x * 1024 + threadIdx.x;
#pragma unroll
    for (int it = 0; it < 4; it++, f4 += 256) {
        size_t off;
        if (f4 < REG_A4) {
            off = (size_t)f4 * 4;
        } else {
            int rem = (f4 - REG_A4) * 4;  // element index in region B (128x4608)
            int row = rem / 4608, col = rem % 4608;
            off = (size_t)(384 + row) * 5632 + col;
        }
        float4 gv = *(const float4*)(g + off);
        float4 uv = *(const float4*)(u + off);
        float4 v;
        v.x = (gv.x / (1.f + __expf(-gv.x))) * uv.x;
        v.y = (gv.y / (1.f + __expf(-gv.y))) * uv.y;
        v.z = (gv.z / (1.f + __expf(-gv.z))) * uv.z;
        v.w = (gv.w / (1.f + __expf(-gv.w))) * uv.w;
        uint32_t h0 = pack_bf2(v.x, v.y), h1 = pack_bf2(v.z, v.w);
        *(uint32_t*)(hi + off)     = h0;
        *(uint32_t*)(hi + off + 2) = h1;
        __nv_bfloat162 a0 = *(__nv_bfloat162*)&h0;
        __nv_bfloat162 a1 = *(__nv_bfloat162*)&h1;
        *(uint32_t*)(lo + off) =
            pack_bf2(v.x - __bfloat162float(a0.x), v.y - __bfloat162float(a0.y));
        *(uint32_t*)(lo + off + 2) =
            pack_bf2(v.z - __bfloat162float(a1.x), v.w - __bfloat162float(a1.y));
    }
}

// ==================== fused: reduce + residual + rmsnorm + splits ==========
template <int BIAS, int RES>
__global__ void fused_rms(const float* __restrict__ P0, const float* __restrict__ P1,
                          const float* __restrict__ aux, const float* __restrict__ w,
                          float* __restrict__ y,
                          __nv_bfloat16* __restrict__ yhi, __nv_bfloat16* __restrict__ ylo,
                          __nv_bfloat16* __restrict__ rhi, __nv_bfloat16* __restrict__ rlo)
{
    const int row = blockIdx.x;
    const int tid = threadIdx.x;
    const size_t b4 = (size_t)row * 512;
    float4 x[2];
    float ss = 0.f;
#pragma unroll
    for (int k = 0; k < 2; k++) {
        size_t i = b4 + tid + k * 256;
        float4 a = ((const float4*)P0)[i];
        float4 b = ((const float4*)P1)[i];
        float4 v = make_float4(a.x + b.x, a.y + b.y, a.z + b.z, a.w + b.w);
        if (BIAS) {
            float bb = aux[row];
            v.x += bb; v.y += bb; v.z += bb; v.w += bb;
        } else {
            float4 c = ((const float4*)aux)[i];
            v.x += c.x; v.y += c.y; v.z += c.z; v.w += c.w;
        }
        x[k] = v;
        ss += v.x * v.x + v.y * v.y + v.z * v.z + v.w * v.w;
    }
    __shared__ float red[256];
    red[tid] = ss;
    __syncthreads();
    for (int s = 128; s > 0; s >>= 1) {
        if (tid < s) red[tid] += red[tid + s];
        __syncthreads();
    }
    const float inv = rsqrtf(red[0] * (1.f / 2048.f) + 1e-6f);
#pragma unroll
    for (int k = 0; k < 2; k++) {
        size_t i = b4 + tid + k * 256;
        float4 v = x[k];
        if (RES) {
            uint32_t h0 = pack_bf2(v.x, v.y), h1 = pack_bf2(v.z, v.w);
            ((uint32_t*)rhi)[i * 2]     = h0;
            ((uint32_t*)rhi)[i * 2 + 1] = h1;
            __nv_bfloat162 a0 = *(__nv_bfloat162*)&h0;
            __nv_bfloat162 a1 = *(__nv_bfloat162*)&h1;
            ((uint32_t*)rlo)[i * 2] =
                pack_bf2(v.x - __bfloat162float(a0.x), v.y - __bfloat162float(a0.y));
            ((uint32_t*)rlo)[i * 2 + 1] =
                pack_bf2(v.z - __bfloat162float(a1.x), v.w - __bfloat162float(a1.y));
        }
        float4 wv = ((const float4*)w)[tid + k * 256];
        float4 yv = make_float4(v.x * inv * wv.x, v.y * inv * wv.y,
                                v.z * inv * wv.z, v.w * inv * wv.w);
        ((float4*)y)[i] = yv;
        uint32_t h0 = pack_bf2(yv.x, yv.y), h1 = pack_bf2(yv.z, yv.w);
        ((uint32_t*)yhi)[i * 2]     = h0;
        ((uint32_t*)yhi)[i * 2 + 1] = h1;
        __nv_bfloat162 a0 = *(__nv_bfloat162*)&h0;
        __nv_bfloat162 a1 = *(__nv_bfloat162*)&h1;
        ((uint32_t*)ylo)[i * 2] =
            pack_bf2(yv.x - __bfloat162float(a0.x), yv.y - __bfloat162float(a0.y));
        ((uint32_t*)ylo)[i * 2 + 1] =
            pack_bf2(yv.z - __bfloat162float(a1.x), yv.w - __bfloat162float(a1.y));
    }
}

__global__ void reduce_out(const float* __restrict__ P0, const float* __restrict__ P1,
                           const float* __restrict__ aux, float* __restrict__ C, int n4)
{
    int i = blockIdx.x * 1024 + threadIdx.x;
#pragma unroll
    for (int u = 0; u < 4; u++, i += 256) {
        if (i < n4) {
            float4 a = ((const float4*)P0)[i];
            float4 b = ((const float4*)P1)[i];
            float4 c = ((const float4*)aux)[i];
            ((float4*)C)[i] = make_float4(a.x + b.x + c.x, a.y + b.y + c.y,
                                          a.z + b.z + c.z, a.w + b.w + c.w);
        }
    }
}

__global__ void reduce_kv(const float* __restrict__ pk0, const float* __restrict__ pk1,
                          const float* __restrict__ pv0, const float* __restrict__ pv1,
                          __nv_bfloat16* __restrict__ k_hi, __nv_bfloat16* __restrict__ k_lo,
                          __nv_bfloat16* __restrict__ v_hi, __nv_bfloat16* __restrict__ v_lo,
                          int n4each)
{
    int blk = blockIdx.x;
    const float *P0, *P1;
    __nv_bfloat16 *hi, *lo;
    int nblk = (n4each + 1023) / 1024;
    if (blk < nblk) { P0 = pk0; P1 = pk1; hi = k_hi; lo = k_lo; }
    else { blk -= nblk; P0 = pv0; P1 = pv1; hi = v_hi; lo = v_lo; }
    int i = blk * 1024 + threadIdx.x;
#pragma unroll
    for (int u = 0; u < 4; u++, i += 256) {
        if (i < n4each) {
            float4 a = ((const float4*)P0)[i];
            float4 b = ((const float4*)P1)[i];
            float4 v = make_float4(a.x + b.x, a.y + b.y, a.z + b.z, a.w + b.w);
            uint32_t h0 = pack_bf2(v.x, v.y), h1 = pack_bf2(v.z, v.w);
            ((uint32_t*)hi)[i * 2]     = h0;
            ((uint32_t*)hi)[i * 2 + 1] = h1;
            __nv_bfloat162 a0 = *(__nv_bfloat162*)&h0;
            __nv_bfloat162 a1 = *(__nv_bfloat162*)&h1;
            ((uint32_t*)lo)[i * 2] =
                pack_bf2(v.x - __bfloat162float(a0.x), v.y - __bfloat162float(a0.y));
            ((uint32_t*)lo)[i * 2 + 1] =
                pack_bf2(v.z - __bfloat162float(a1.x), v.w - __bfloat162float(a1.y));
        }
    }
}

// ==================== mega split ====================
struct SplitArgs {
    const float* src[9];
    __nv_bfloat16* hi[9];
    __nv_bfloat16* lo[9];
    int blk_start[10];
    int n4[9];
};

__global__ void megasplit_kernel(SplitArgs a)
{
    int blk = blockIdx.x;
    int j = 0;
#pragma unroll
    for (int t = 1; t < 9; t++)
        if (blk >= a.blk_start[t]) j = t;
    const float* src = a.src[j];
    __nv_bfloat16* hi = a.hi[j];
    __nv_bfloat16* lo = a.lo[j];
    const int n4 = a.n4[j];
    int i = (blk - a.blk_start[j]) * 1024 + threadIdx.x;
#pragma unroll
    for (int u = 0; u < 4; u++, i += 256) {
        if (i < n4) {
            float4 v = ((const float4*)src)[i];
            uint32_t h0 = pack_bf2(v.x, v.y), h1 = pack_bf2(v.z, v.w);
            ((uint32_t*)hi)[i * 2]     = h0;
            ((uint32_t*)hi)[i * 2 + 1] = h1;
            __nv_bfloat162 a0 = *(__nv_bfloat162*)&h0;
            __nv_bfloat162 a1 = *(__nv_bfloat162*)&h1;
            ((uint32_t*)lo)[i * 2] =
                pack_bf2(v.x - __bfloat162float(a0.x), v.y - __bfloat162float(a0.y));
            ((uint32_t*)lo)[i * 2 + 1] =
                pack_bf2(v.z - __bfloat162float(a1.x), v.w - __bfloat162float(a1.y));
        }
    }
}

// ==================== HMMA split-bf16 flash attention ======================
__global__ __launch_bounds__(128, 4) void attn_mma(
    const __nv_bfloat16* __restrict__ Qhi, const __nv_bfloat16* __restrict__ Qlo,
    const __nv_bfloat16* __restrict__ Khi, const __nv_bfloat16* __restrict__ Klo,
    const __nv_bfloat16* __restrict__ Vhi, const __nv_bfloat16* __restrict__ Vlo,
    __nv_bfloat16* __restrict__ Ohi, __nv_bfloat16* __restrict__ Olo)
{
    extern __shared__ char sm[];
    const int tid = threadIdx.x;
    const int wid = tid >> 5, lid = tid & 31;
    const int q0 = blockIdx.x * 64;
    const int head = blockIdx.y;
    const int kvoff = (head >> 2) * 64;
    const uint32_t sb = smem_u32(sm);
    const uint32_t sQh = sb, sQl = sb + 8192;
    const uint32_t sKV = sb + 16384;

#pragma unroll
    for (int i = 0; i < 4; i++) {
        int f = tid + i * 128;
        int r = f >> 3, c = f & 7;
        uint32_t off = (uint32_t)(r * 128) + (uint32_t)((c * 16) ^ ((r & 7) << 4));
        size_t g = (size_t)(q0 + r) * 2048 + head * 64 + c * 8;
        CP_ASYNC16(sQh + off, Qhi + g);
        CP_ASYNC16(sQl + off, Qlo + g);
    }
    CP_COMMIT();

#define ISSUE_KV(t0, st)                                                       \
    {                                                                          \
        uint32_t s_ = sKV + (uint32_t)(st) * 16384;                            \
        _Pragma("unroll")                                                      \
        for (int i_ = 0; i_ < 2; i_++) {                                       \
            int f_ = tid + i_ * 128;                                           \
            int r_ = f_ >> 3, c_ = f_ & 7;                                     \
            uint32_t o_ = (uint32_t)(r_ * 128) +                               \
                          (uint32_t)((c_ * 16) ^ ((r_ & 7) << 4));             \
            size_t g_ = (size_t)((t0) + r_) * 512 + kvoff + c_ * 8;            \
            CP_ASYNC16(s_ + o_,         Khi + g_);                             \
            CP_ASYNC16(s_ + 4096 + o_,  Klo + g_);                             \
            CP_ASYNC16(s_ + 8192 + o_,  Vhi + g_);                             \
            CP_ASYNC16(s_ + 12288 + o_, Vlo + g_);                             \
        }                                                                      \
    }

    ISSUE_KV(0, 0);  CP_COMMIT();
    ISSUE_KV(32, 1); CP_COMMIT();

    CP_WAIT1();
    __syncthreads();

    uint32_t qh[4][4], ql[4][4];
    {
        const int ar = (lid & 7) + ((lid >> 3) & 1) * 8;
        const int row = wid * 16 + ar;
        const uint32_t khalf = (uint32_t)((lid >> 4) & 1) * 16;
#pragma unroll
        for (int ks = 0; ks < 4; ks++) {
            uint32_t off = (uint32_t)(row * 128) +
                           ((khalf + (uint32_t)ks * 32) ^ ((uint32_t)(ar & 7) << 4));
            LDSM_X4(qh[ks][0], qh[ks][1], qh[ks][2], qh[ks][3], sQh + off);
            LDSM_X4(ql[ks][0], ql[ks][1], ql[ks][2], ql[ks][3], sQl + off);
        }
    }

    float acc_o[8][4];
#pragma unroll
    for (int d = 0; d < 8; d++)
#pragma unroll
        for (int e = 0; e < 4; e++) acc_o[d][e] = 0.f;
    float mr0 = -1e30f, mr1 = -1e30f, lr0 = 0.f, lr1 = 0.f;

    const int brS = (lid & 7) + ((lid >> 4) & 1) * 8;
    const uint32_t bkS = (uint32_t)((lid >> 3) & 1) * 16;
    const int trV = (lid & 7) + ((lid >> 3) & 1) * 8;
    const uint32_t dkV = (uint32_t)((lid >> 4) & 1) * 16;

    for (int t = 0; t < 96; t++) {
        const uint32_t st = sKV + (uint32_t)(t & 1) * 16384;

        float s[4][4];
#pragma unroll
        for (int nt = 0; nt < 4; nt++)
#pragma unroll
            for (int e = 0; e < 4; e++) s[nt][e] = 0.f;
#pragma unroll
        for (int ks = 0; ks < 4; ks++) {
            uint32_t bh[4][2], bl[4][2];
#pragma unroll
            for (int p = 0; p < 2; p++) {
                int rr = p * 16 + brS;
                uint32_t off = (uint32_t)(rr * 128) +
                               ((bkS + (uint32_t)ks * 32) ^ ((uint32_t)(rr & 7) << 4));
                LDSM_X4(bh[2*p][0], bh[2*p][1], bh[2*p+1][0], bh[2*p+1][1], st + off);
                LDSM_X4(bl[2*p][0], bl[2*p][1], bl[2*p+1][0], bl[2*p+1][1], st + 4096 + off);
            }
#pragma unroll
            for (int nt = 0; nt < 4; nt++) {
                MMA_BF16(s[nt], qh[ks], bh[nt]);
                MMA_BF16(s[nt], qh[ks], bl[nt]);
                MMA_BF16(s[nt], ql[ks], bh[nt]);
            }
        }

        float mn0 = mr0, mn1 = mr1;
#pragma unroll
        for (int nt = 0; nt < 4; nt++) {
            s[nt][0] *= 0.125f; s[nt][1] *= 0.125f;
            s[nt][2] *= 0.125f; s[nt][3] *= 0.125f;
            mn0 = fmaxf(mn0, fmaxf(s[nt][0], s[nt][1]));
            mn1 = fmaxf(mn1, fmaxf(s[nt][2], s[nt][3]));
        }
        mn0 = fmaxf(mn0, __shfl_xor_sync(0xffffffffu, mn0, 1));
        mn0 = fmaxf(mn0, __shfl_xor_sync(0xffffffffu, mn0, 2));
        mn1 = fmaxf(mn1, __shfl_xor_sync(0xffffffffu, mn1, 1));
        mn1 = fmaxf(mn1, __shfl_xor_sync(0xffffffffu, mn1, 2));
        float f0 = __expf(mr0 - mn0), f1 = __expf(mr1 - mn1);
        mr0 = mn0; mr1 = mn1;
        float ps0 = 0.f, ps1 = 0.f;
#pragma unroll
        for (int nt = 0; nt < 4; nt++) {
            s[nt][0] = __expf(s[nt][0] - mn0);
            s[nt][1] = __expf(s[nt][1] - mn0);
            s[nt][2] = __expf(s[nt][2] - mn1);
            s[nt][3] = __expf(s[nt][3] - mn1);
            ps0 += s[nt][0] + s[nt][1];
            ps1 += s[nt][2] + s[nt][3];
        }
        lr0 = lr0 * f0 + ps0;
        lr1 = lr1 * f1 + ps1;
#pragma unroll
        for (int d = 0; d < 8; d++) {
            acc_o[d][0] *= f0; acc_o[d][1] *= f0;
            acc_o[d][2] *= f1; acc_o[d][3] *= f1;
        }

#pragma unroll
        for (int j = 0; j < 2; j++) {
            uint32_t ah[4], al[4];
            {
                float p00 = s[2*j][0],   p01 = s[2*j][1];
                float p02 = s[2*j][2],   p03 = s[2*j][3];
                float p10 = s[2*j+1][0], p11 = s[2*j+1][1];
                float p12 = s[2*j+1][2], p13 = s[2*j+1][3];
                ah[0] = pack_bf2(p00, p01); ah[1] = pack_bf2(p02, p03);
                ah[2] = pack_bf2(p10, p11); ah[3] = pack_bf2(p12, p13);
#pragma unroll
                for (int e = 0; e < 4; e++) {
                    __nv_bfloat162 hh = *(__nv_bfloat162*)&ah[e];
                    float x0, x1;
                    if (e == 0) { x0 = p00; x1 = p01; }
                    else if (e == 1) { x0 = p02; x1 = p03; }
                    else if (e == 2) { x0 = p10; x1 = p11; }
                    else { x0 = p12; x1 = p13; }
                    al[e] = pack_bf2(x0 - __bfloat162float(hh.x),
                                     x1 - __bfloat162float(hh.y));
                }
            }
            const int rr = j * 16 + trV;
#pragma unroll
            for (int dp = 0; dp < 4; dp++) {
                uint32_t off = (uint32_t)(rr * 128) +
                               ((dkV + (uint32_t)dp * 32) ^ ((uint32_t)(rr & 7) << 4));
                uint32_t vh[4], vl[4];
                LDSM_X4_T(vh[0], vh[1], vh[2], vh[3], st + 8192 + off);
                LDSM_X4_T(vl[0], vl[1], vl[2], vl[3], st + 12288 + off);
                uint32_t b0h[2] = {vh[0], vh[1]}, b1h[2] = {vh[2], vh[3]};
                uint32_t b0l[2] = {vl[0], vl[1]}, b1l[2] = {vl[2], vl[3]};
                MMA_BF16(acc_o[2*dp],   ah, b0h);
                MMA_BF16(acc_o[2*dp],   ah, b0l);
                MMA_BF16(acc_o[2*dp],   al, b0h);
                MMA_BF16(acc_o[2*dp+1], ah, b1h);
                MMA_BF16(acc_o[2*dp+1], ah, b1l);
                MMA_BF16(acc_o[2*dp+1], al, b1h);
            }
        }

        __syncthreads();
        if (t + 2 < 96) ISSUE_KV((t + 2) * 32, t & 1);
        CP_COMMIT();
        if (t + 1 < 96) { CP_WAIT1(); __syncthreads(); }
    }

    lr0 += __shfl_xor_sync(0xffffffffu, lr0, 1);
    lr0 += __shfl_xor_sync(0xffffffffu, lr0, 2);
    lr1 += __shfl_xor_sync(0xffffffffu, lr1, 1);
    lr1 += __shfl_xor_sync(0xffffffffu, lr1, 2);
    float il0 = 1.f / lr0, il1 = 1.f / lr1;
    const int row0 = q0 + wid * 16 + (lid >> 2);
    const int col0 = head * 64 + (lid & 3) * 2;
#pragma unroll
    for (int d = 0; d < 8; d++) {
        int col = col0 + d * 8;
        float o0 = acc_o[d][0] * il0, o1 = acc_o[d][1] * il0;
        float o2 = acc_o[d][2] * il1, o3 = acc_o[d][3] * il1;
        uint32_t h0 = pack_bf2(o0, o1), h1 = pack_bf2(o2, o3);
        *(uint32_t*)(Ohi + (size_t)row0 * 2048 + col) = h0;
        *(uint32_t*)(Ohi + (size_t)(row0 + 8) * 2048 + col) = h1;
        __nv_bfloat162 hh0 = *(__nv_bfloat162*)&h0;
        __nv_bfloat162 hh1 = *(__nv_bfloat162*)&h1;
        *(uint32_t*)(Olo + (size_t)row0 * 2048 + col) =
            pack_bf2(o0 - __bfloat162float(hh0.x), o1 - __bfloat162float(hh0.y));
        *(uint32_t*)(Olo + (size_t)(row0 + 8) * 2048 + col) =
            pack_bf2(o2 - __bfloat162float(hh1.x), o3 - __bfloat162float(hh1.y));
    }
}

// -------------------- misc elementwise --------------------
__global__ void transpose_split(const float* __restrict__ x,
                                __nv_bfloat16* __restrict__ hiT,
                                __nv_bfloat16* __restrict__ loT, int R, int C)
{
    __shared__ float t[32][33];
    int c0 = blockIdx.x * 32, r0 = blockIdx.y * 32;
    for (int i = threadIdx.y; i < 32; i += 8)
        t[i][threadIdx.x] = x[(size_t)(r0 + i) * C + c0 + threadIdx.x];
    __syncthreads();
    for (int i = threadIdx.y; i < 32; i += 8) {
        float v = t[threadIdx.x][i];
        __nv_bfloat16 h = __float2bfloat16(v);
        size_t o = (size_t)(c0 + i) * R + r0 + threadIdx.x;
        hiT[o] = h;
        loT[o] = __float2bfloat16(v - __bfloat162float(h));
    }
}

// -------------------- orchestration --------------------
static const int SMEM_GEMM = 3 * 32768;
static const int SMEM_ATTN = 16384 + 2 * 16384;

extern "C" void kernel_launch(void* const* d_in, const int* in_sizes, int n_in,
                              void* d_out, int out_size)
{
    (void)in_sizes; (void)n_in; (void)out_size;
    const float* hidden      = (const float*)d_in[0];
    const float* comp_w      = (const float*)d_in[1];
    const float* comp_b      = (const float*)d_in[2];
    const float* q_w         = (const float*)d_in[3];
    const float* k_w         = (const float*)d_in[4];
    const float* v_w         = (const float*)d_in[5];
    const float* o_w         = (const float*)d_in[6];
    const float* attn_norm_w = (const float*)d_in[7];
    const float* mlp_norm_w  = (const float*)d_in[8];
    const float* gate_w      = (const float*)d_in[9];
    const float* up_w        = (const float*)d_in[10];
    const float* down_w      = (const float*)d_in[11];
    float* out = (float*)d_out;

    cudaFuncSetAttribute(bgemm_splitk, cudaFuncAttributeMaxDynamicSharedMemorySize, SMEM_GEMM);
    cudaFuncSetAttribute(bgemm_qkv,    cudaFuncAttributeMaxDynamicSharedMemorySize, SMEM_GEMM);
    cudaFuncSetAttribute(bgemm_gateup, cudaFuncAttributeMaxDynamicSharedMemorySize, SMEM_GEMM);
    cudaFuncSetAttribute(attn_mma,     cudaFuncAttributeMaxDynamicSharedMemorySize, SMEM_ATTN);

    float *ct, *gate, *up, *p0, *p1, *pk0, *pk1, *pv0, *pv1, *pg0, *pg1;
    cudaGetSymbolAddress((void**)&ct,   g_ct);
    cudaGetSymbolAddress((void**)&gate, g_gate);
    cudaGetSymbolAddress((void**)&up,   g_up);
    cudaGetSymbolAddress((void**)&p0,   g_p0);
    cudaGetSymbolAddress((void**)&p1,   g_p1);
    cudaGetSymbolAddress((void**)&pk0,  g_pk0);
    cudaGetSymbolAddress((void**)&pk1,  g_pk1);
    cudaGetSymbolAddress((void**)&pv0,  g_pv0);
    cudaGetSymbolAddress((void**)&pv1,  g_pv1);
    cudaGetSymbolAddress((void**)&pg0,  g_pg0);
    cudaGetSymbolAddress((void**)&pg1,  g_pg1);

    __nv_bfloat16 *res_hi, *res_lo, *ct_hi, *ct_lo, *ao_hi, *ao_lo, *ga_hi, *ga_lo,
                  *hT_hi, *hT_lo, *q_hi, *q_lo, *k_hi, *k_lo, *v_hi, *v_lo,
                  *cw_hi, *cw_lo, *qw_hi, *qw_lo, *kw_hi, *kw_lo,
                  *vw_hi, *vw_lo, *ow_hi, *ow_lo, *gw_hi, *gw_lo, *uw_hi, *uw_lo,
                  *dw_hi, *dw_lo;
    cudaGetSymbolAddress((void**)&res_hi, g_res_hi); cudaGetSymbolAddress((void**)&res_lo, g_res_lo);
    cudaGetSymbolAddress((void**)&ct_hi,  g_ct_hi);  cudaGetSymbolAddress((void**)&ct_lo,  g_ct_lo);
    cudaGetSymbolAddress((void**)&ao_hi,  g_ao_hi);  cudaGetSymbolAddress((void**)&ao_lo,  g_ao_lo);
    cudaGetSymbolAddress((void**)&ga_hi,  g_ga_hi);  cudaGetSymbolAddress((void**)&ga_lo,  g_ga_lo);
    cudaGetSymbolAddress((void**)&hT_hi,  g_hT_hi);  cudaGetSymbolAddress((void**)&hT_lo,  g_hT_lo);
    cudaGetSymbolAddress((void**)&q_hi,   g_q_hi);   cudaGetSymbolAddress((void**)&q_lo,   g_q_lo);
    cudaGetSymbolAddress((void**)&k_hi,   g_k_hi);   cudaGetSymbolAddress((void**)&k_lo,   g_k_lo);
    cudaGetSymbolAddress((void**)&v_hi,   g_v_hi);   cudaGetSymbolAddress((void**)&v_lo,   g_v_lo);
    cudaGetSymbolAddress((void**)&cw_hi,  g_cw_hi);  cudaGetSymbolAddress((void**)&cw_lo,  g_cw_lo);
    cudaGetSymbolAddress((void**)&qw_hi,  g_qw_hi);  cudaGetSymbolAddress((void**)&qw_lo,  g_qw_lo);
    cudaGetSymbolAddress((void**)&kw_hi,  g_kw_hi);  cudaGetSymbolAddress((void**)&kw_lo,  g_kw_lo);
    cudaGetSymbolAddress((void**)&vw_hi,  g_vw_hi);  cudaGetSymbolAddress((void**)&vw_lo,  g_vw_lo);
    cudaGetSymbolAddress((void**)&ow_hi,  g_ow_hi);  cudaGetSymbolAddress((void**)&ow_lo,  g_ow_lo);
    cudaGetSymbolAddress((void**)&gw_hi,  g_gw_hi);  cudaGetSymbolAddress((void**)&gw_lo,  g_gw_lo);
    cudaGetSymbolAddress((void**)&uw_hi,  g_uw_hi);  cudaGetSymbolAddress((void**)&uw_lo,  g_uw_lo);
    cudaGetSymbolAddress((void**)&dw_hi,  g_dw_hi);  cudaGetSymbolAddress((void**)&dw_lo,  g_dw_lo);

    // ---- one mega-split launch for all conversions ----
    {
        SplitArgs a;
        const float* srcs[9] = {comp_w, q_w, k_w, v_w, o_w, gate_w, up_w, down_w, hidden};
        __nv_bfloat16* his[9] = {cw_hi, qw_hi, kw_hi, vw_hi, ow_hi, gw_hi, uw_hi, dw_hi, res_hi};
        __nv_bfloat16* los[9] = {cw_lo, qw_lo, kw_lo, vw_lo, ow_lo, gw_lo, uw_lo, dw_lo, res_lo};
        int ns[9] = {1024*2048, 2048*2048, 512*2048, 512*2048, 2048*2048,
                     5632*2048, 5632*2048, 2048*5632, 2048*2048};
        int blk = 0;
        for (int j = 0; j < 9; j++) {
            a.src[j] = srcs[j]; a.hi[j] = his[j]; a.lo[j] = los[j];
            a.n4[j] = ns[j] / 4;
            a.blk_start[j] = blk;
            blk += (a.n4[j] + 1023) / 1024;
        }
        a.blk_start[9] = blk;
        megasplit_kernel<<<blk, 256>>>(a);
    }
    transpose_split<<<dim3(64, 64), dim3(32, 8)>>>(hidden, hT_hi, hT_lo, 2048, 2048);

    const int N4 = 1024 * 2048 / 4;
    const int KV4 = 3072 * 512 / 4;

    bgemm_splitk<<<256, 256, SMEM_GEMM>>>(cw_hi, cw_lo, hT_hi, hT_lo,
                                          p0, p1, 2048, 2048, 1024);
    fused_rms<1,1><<<1024, 256>>>(p0, p1, comp_b, attn_norm_w,
        ct, ct_hi, ct_lo, res_hi + 2048 * 2048, res_lo + 2048 * 2048);

    for (int layer = 0; layer < 2; layer++) {
        bgemm_qkv<<<512, 256, SMEM_GEMM>>>(ct_hi, ct_lo, res_hi, res_lo,
            qw_hi, qw_lo, kw_hi, kw_lo, vw_hi, vw_lo,
            q_hi, q_lo, pk0, pk1, pv0, pv1);
        reduce_kv<<<2 * (KV4 / 1024), 256>>>(pk0, pk1, pv0, pv1,
                                             k_hi, k_lo, v_hi, v_lo, KV4);

        attn_mma<<<dim3(16, 32), 128, SMEM_ATTN>>>(q_hi, q_lo, k_hi, k_lo,
                                                   v_hi, v_lo, ao_hi, ao_lo);

        bgemm_splitk<<<256, 256, SMEM_GEMM>>>(ao_hi, ao_lo, ow_hi, ow_lo,
                                              p0, p1, 2048, 2048, 1024);
        fused_rms<0,0><<<1024, 256>>>(p0, p1, ct, mlp_norm_w,
                                      ct, ct_hi, ct_lo, nullptr, nullptr);

        bgemm_gateup<<<888, 256, SMEM_GEMM>>>(ct_hi, ct_lo, gw_hi, gw_lo,
                                              uw_hi, uw_lo, gate, up, pg0, pg1);
        reduce_up_swiglu<<<736, 256>>>(pg0, pg1, gate, ga_hi, ga_lo);
        swiglu_plain<<<672, 256>>>(gate, up, ga_hi, ga_lo);

        bgemm_splitk<<<256, 256, SMEM_GEMM>>>(ga_hi, ga_lo, dw_hi, dw_lo,
                                              p0, p1, 2048, 5632, 2816);
        if (layer == 0) {
            fused_rms<0,1><<<1024, 256>>>(p0, p1, ct, attn_norm_w,
                ct, ct_hi, ct_lo, res_hi + 2048 * 2048, res_lo + 2048 * 2048);
        } else {
            reduce_out<<<N4 / 1024, 256>>>(p0, p1, ct, out, N4);
        }
    }
}